// round 11
// baseline (speedup 1.0000x reference)
#include <cuda_runtime.h>
#include <cstdint>

// Problem constants
static constexpr int Bb = 2, Ss = 2048, Hh = 16, DH = 64, Dd = 1024;
static constexpr int KC32 = 32;                 // 1024 / 32 k-steps

// Scratch (static device globals — no allocations allowed)
__device__ float g_q[Bb * Hh * Ss * DH];        // rope'd, scaled(*log2e), tf32
__device__ float g_k[Bb * Hh * Ss * DH];
__device__ float g_v[Bb * Hh * Ss * DH];
__device__ float g_xp[32 * 4096 * 36];          // packed A gemm1 (tf32, pad 36)
__device__ float g_wp[32 * 24 * 4352];          // packed B w_qkv
__device__ float g_wop[32 * 8 * 4352];          // packed B w_out
__device__ float g_aop[32 * 4096 * 36];         // packed A gemm2 (attn out)
__device__ float g_cos[Ss * DH];                // cos(freqs)
__device__ float g_sin[Ss * DH];                // sin(freqs)

__device__ __forceinline__ uint32_t f2tf(float f) {
    uint32_t u;
    asm("cvt.rna.tf32.f32 %0, %1;" : "=r"(u) : "f"(f));
    return u;
}
__device__ __forceinline__ float f2tff(float f) { return __uint_as_float(f2tf(f)); }

__device__ __forceinline__ float ex2(float x) {
    float y;
    asm("ex2.approx.f32 %0, %1;" : "=f"(y) : "f"(x));
    return y;
}

__device__ __forceinline__ void cp16(void* smem_ptr, const void* gptr) {
    uint32_t sa = (uint32_t)__cvta_generic_to_shared(smem_ptr);
    asm volatile("cp.async.ca.shared.global [%0], [%1], 16;"
                 :: "r"(sa), "l"(gptr));
}

__device__ __forceinline__ void mma8(float (&c)[4], const uint32_t (&a)[4],
                                     uint32_t b0, uint32_t b1) {
    asm volatile(
        "mma.sync.aligned.m16n8k8.row.col.f32.tf32.tf32.f32 "
        "{%0,%1,%2,%3}, {%4,%5,%6,%7}, {%8,%9}, {%0,%1,%2,%3};"
        : "+f"(c[0]), "+f"(c[1]), "+f"(c[2]), "+f"(c[3])
        : "r"(a[0]), "r"(a[1]), "r"(a[2]), "r"(a[3]), "r"(b0), "r"(b1));
}

// ---- mbarrier + 1D bulk-copy helpers ----
__device__ __forceinline__ uint32_t s2u(const void* p) {
    return (uint32_t)__cvta_generic_to_shared(p);
}
__device__ __forceinline__ void mbar_init(uint32_t addr, uint32_t cnt) {
    asm volatile("mbarrier.init.shared.b64 [%0], %1;" :: "r"(addr), "r"(cnt));
}
__device__ __forceinline__ void mbar_expect_tx(uint32_t addr, uint32_t bytes) {
    asm volatile("mbarrier.arrive.expect_tx.shared.b64 _, [%0], %1;"
                 :: "r"(addr), "r"(bytes));
}
__device__ __forceinline__ void mbar_wait(uint32_t addr, uint32_t parity) {
    asm volatile(
        "{\n\t.reg .pred P;\n"
        "W%=:\n\t"
        "mbarrier.try_wait.parity.shared.b64 P, [%0], %1;\n\t"
        "@!P bra W%=;\n\t}"
        :: "r"(addr), "r"(parity) : "memory");
}
__device__ __forceinline__ void bulk_g2s(uint32_t dst, const void* src,
                                         uint32_t bytes, uint32_t mbar) {
    asm volatile(
        "cp.async.bulk.shared::cta.global.mbarrier::complete_tx::bytes "
        "[%0], [%1], %2, [%3];"
        :: "r"(dst), "l"(src), "r"(bytes), "r"(mbar) : "memory");
}

// ---------------------------------------------------------------------------
// Pack kernels: contiguous, padded, tf32-rounded tiles (BK=32 layouts).
// A: X[M][1024] -> Xp[kc][M][36]  (cols 0-31 data, 32-35 pad)
// ---------------------------------------------------------------------------
__global__ __launch_bounds__(256) void pack_a(
    const float* __restrict__ X, float* __restrict__ Xp) {
    int idx = blockIdx.x * 256 + threadIdx.x;   // over 4096*1024
    int m = idx >> 10, k = idx & 1023;
    Xp[((size_t)(k >> 5) * 4096 + m) * 36 + (k & 31)] = f2tff(X[idx]);
}

// B: W[1024][N] -> Wp[kc][nb][kr(32)][136]  (cols 0-127 data, pad 8)
__global__ __launch_bounds__(256) void pack_b(
    const float* __restrict__ W, float* __restrict__ Wp, int N) {
    int idx = blockIdx.x * 256 + threadIdx.x;   // over 1024*N
    int k = idx / N, n = idx - k * N;
    size_t chunk = (size_t)(k >> 5) * (N >> 7) + (n >> 7);
    Wp[chunk * 4352 + (k & 31) * 136 + (n & 127)] = f2tff(W[idx]);
}

// cos/sin tables for the fused-rope GEMM epilogue (precise sincosf, once).
__global__ __launch_bounds__(256) void trig_kernel(
    const float* __restrict__ freqs, float* __restrict__ cb,
    float* __restrict__ sb) {
    int i = blockIdx.x * 256 + threadIdx.x;     // 2048*64
    float s, c;
    sincosf(freqs[i], &s, &c);
    cb[i] = c;
    sb[i] = s;
}

// ---------------------------------------------------------------------------
// Shared GEMM mainloop: 128x128 tile, BK=32, 8 warps as 4x2 of 32x64 tiles,
// 3-stage mbarrier + bulk pipeline, sized for 2 CTAs/SM (107.5KB smem, <=128
// regs via launch_bounds(256,2)). Each warp's 64-col slice = one head.
// ---------------------------------------------------------------------------
static constexpr int AST_W = 128 * 36;          // 4608 words
static constexpr int BST_W = 32 * 136;          // 4352 words
static constexpr int STG_W = AST_W + BST_W;     // 8960 words = 35840 B
static constexpr int GEMM_SMEM = 3 * STG_W * 4; // 107520 B

#define GEMM_MAINLOOP(ApPtr, BpPtr, NBv)                                      \
    extern __shared__ uint32_t gsm[];                                         \
    __shared__ uint64_t gmb[3];                                               \
    const int tid = threadIdx.x, lane = tid & 31, warp = tid >> 5;            \
    const int wm = (warp >> 1) * 32, wn = (warp & 1) * 64;                    \
    const int lr = lane >> 2, lq = lane & 3;                                  \
    const int bm = blockIdx.y * 128, nb = blockIdx.x;                         \
    const uint32_t mb0 = s2u(gmb);                                            \
    const uint32_t smem_base = s2u(gsm);                                      \
    if (tid == 0) {                                                           \
        mbar_init(mb0, 1);                                                    \
        mbar_init(mb0 + 8, 1);                                                \
        mbar_init(mb0 + 16, 1);                                               \
        asm volatile("fence.proxy.async.shared::cta;" ::: "memory");          \
    }                                                                         \
    __syncthreads();                                                          \
    auto issue = [&](int i) {                                                 \
        if (tid == 0) {                                                       \
            int st = i % 3;                                                   \
            uint32_t m = mb0 + st * 8;                                        \
            uint32_t dst = smem_base + st * (STG_W * 4);                      \
            mbar_expect_tx(m, STG_W * 4);                                     \
            bulk_g2s(dst, (ApPtr) + ((size_t)i * 4096 + bm) * 36,             \
                     AST_W * 4, m);                                           \
            bulk_g2s(dst + AST_W * 4, (BpPtr) + (size_t)(i * (NBv) + nb) *    \
                     BST_W, BST_W * 4, m);                                    \
        }                                                                     \
    };                                                                        \
    float acc[2][8][4];                                                       \
    _Pragma("unroll") for (int mt = 0; mt < 2; mt++)                          \
        _Pragma("unroll") for (int nt = 0; nt < 8; nt++)                      \
            _Pragma("unroll") for (int i = 0; i < 4; i++)                     \
                acc[mt][nt][i] = 0.f;                                         \
    issue(0);                                                                 \
    issue(1);                                                                 \
    issue(2);                                                                 \
    for (int i = 0; i < KC32; i++) {                                          \
        const int st = i % 3;                                                 \
        mbar_wait(mb0 + st * 8, (i / 3) & 1);                                 \
        const uint32_t* As = gsm + st * STG_W;                                \
        const uint32_t* Bs = As + AST_W;                                      \
        _Pragma("unroll") for (int ks = 0; ks < 32; ks += 8) {                \
            uint32_t a[2][4], b[8][2];                                        \
            _Pragma("unroll") for (int mt = 0; mt < 2; mt++) {                \
                int r0 = (wm + mt * 16 + lr) * 36, c0 = ks + lq;              \
                a[mt][0] = As[r0 + c0];                                       \
                a[mt][1] = As[r0 + 288 + c0];                                 \
                a[mt][2] = As[r0 + c0 + 4];                                   \
                a[mt][3] = As[r0 + 288 + c0 + 4];                             \
            }                                                                 \
            _Pragma("unroll") for (int nt = 0; nt < 8; nt++) {                \
                int cc = wn + nt * 8 + lr, kr = ks + lq;                      \
                b[nt][0] = Bs[kr * 136 + cc];                                 \
                b[nt][1] = Bs[(kr + 4) * 136 + cc];                           \
            }                                                                 \
            _Pragma("unroll") for (int mt = 0; mt < 2; mt++)                  \
                _Pragma("unroll") for (int nt = 0; nt < 8; nt++)              \
                    mma8(acc[mt][nt], a[mt], b[nt][0], b[nt][1]);             \
        }                                                                     \
        __syncthreads();                                                      \
        if (i + 3 < KC32) issue(i + 3);                                       \
    }

// ---------------------------------------------------------------------------
// GEMM 1: QKV projection with FUSED RoPE epilogue.
// Warp's 64-col slice = one (type, head); RoPE partners nt / nt+4 in-warp.
// ---------------------------------------------------------------------------
__global__ __launch_bounds__(256, 2) void gemm_qkv(
    const float* __restrict__ Ap, const float* __restrict__ Bp,
    float* __restrict__ Qo, float* __restrict__ Ko, float* __restrict__ Vo,
    const float* __restrict__ cb, const float* __restrict__ sb) {
    GEMM_MAINLOOP(Ap, Bp, 24)

    const int col0 = nb * 128 + wn;             // 64-col slice start
    const int type = col0 >> 10;                // 0=q, 1=k, 2=v
    const int h = (col0 >> 6) & 15;
    const float qsc = 0.125f * 1.4426950408889634f;

    if (type < 2) {
        float* dst0 = (type == 0) ? Qo : Ko;
#pragma unroll
        for (int mt = 0; mt < 2; mt++) {
#pragma unroll
            for (int e2 = 0; e2 < 2; e2++) {
                int r = bm + wm + mt * 16 + lr + 8 * e2;
                int s = r & 2047, bb = r >> 11;
                float* dst = dst0 + ((size_t)(bb * Hh + h) * Ss + s) * 64;
                const float* cr = cb + s * 64;
                const float* sr = sb + s * 64;
#pragma unroll
                for (int nt = 0; nt < 4; nt++) {
                    int dlo = nt * 8 + (lq << 1);
                    float2 clo = *(const float2*)&cr[dlo];
                    float2 slo = *(const float2*)&sr[dlo];
                    float2 chi = *(const float2*)&cr[dlo + 32];
                    float2 shi = *(const float2*)&sr[dlo + 32];
                    float al0 = acc[mt][nt][2 * e2], al1 = acc[mt][nt][2 * e2 + 1];
                    float ah0 = acc[mt][nt + 4][2 * e2], ah1 = acc[mt][nt + 4][2 * e2 + 1];
                    float ol0 = al0 * clo.x - ah0 * slo.x;
                    float ol1 = al1 * clo.y - ah1 * slo.y;
                    float oh0 = ah0 * chi.x + al0 * shi.x;
                    float oh1 = ah1 * chi.y + al1 * shi.y;
                    if (type == 0) { ol0 *= qsc; ol1 *= qsc; oh0 *= qsc; oh1 *= qsc; }
                    *(float2*)&dst[dlo] = make_float2(f2tff(ol0), f2tff(ol1));
                    *(float2*)&dst[dlo + 32] = make_float2(f2tff(oh0), f2tff(oh1));
                }
            }
        }
    } else {
#pragma unroll
        for (int mt = 0; mt < 2; mt++) {
#pragma unroll
            for (int e2 = 0; e2 < 2; e2++) {
                int r = bm + wm + mt * 16 + lr + 8 * e2;
                int s = r & 2047, bb = r >> 11;
                float* dst = Vo + ((size_t)(bb * Hh + h) * Ss + s) * 64;
#pragma unroll
                for (int nt = 0; nt < 8; nt++) {
                    int d = nt * 8 + (lq << 1);
                    *(float2*)&dst[d] =
                        make_float2(f2tff(acc[mt][nt][2 * e2]),
                                    f2tff(acc[mt][nt][2 * e2 + 1]));
                }
            }
        }
    }
}

// ---------------------------------------------------------------------------
// GEMM 2: output projection, plain row-major epilogue.
// ---------------------------------------------------------------------------
__global__ __launch_bounds__(256, 2) void gemm_out(
    const float* __restrict__ Ap, const float* __restrict__ Bp,
    float* __restrict__ C) {
    GEMM_MAINLOOP(Ap, Bp, 8)

#pragma unroll
    for (int mt = 0; mt < 2; mt++)
#pragma unroll
        for (int nt = 0; nt < 8; nt++) {
            int row = bm + wm + mt * 16 + lr;
            int col = (nb << 7) + wn + nt * 8 + (lq << 1);
            *(float2*)&C[(size_t)row * 1024 + col] =
                make_float2(acc[mt][nt][0], acc[mt][nt][1]);
            *(float2*)&C[(size_t)(row + 8) * 1024 + col] =
                make_float2(acc[mt][nt][2], acc[mt][nt][3]);
        }
}

// ---------------------------------------------------------------------------
// Causal flash attention (R6/R10 proven core, unchanged). Br=128, Bc=64.
// Epilogue writes PACKED A for gemm2: aop[kc][row][36], kc = (h*64+d)>>5.
// ---------------------------------------------------------------------------
static constexpr int KS_WORDS = 64 * 68;
static constexpr int VS_WORDS = 64 * 72;
static constexpr int ATTN_SMEM_BYTES = (2 * KS_WORDS + 2 * VS_WORDS) * 4;  // 71680

__global__ __launch_bounds__(256) void attn_kernel(
    const float* __restrict__ Q, const float* __restrict__ K,
    const float* __restrict__ V, float* __restrict__ AOP) {
    extern __shared__ uint32_t dynsmem[];
    uint32_t (*Ks)[64][68] = reinterpret_cast<uint32_t (*)[64][68]>(dynsmem);
    uint32_t (*Vs)[64][72] =
        reinterpret_cast<uint32_t (*)[64][72]>(dynsmem + 2 * KS_WORDS);

    const int qt = gridDim.x - 1 - blockIdx.x;
    const int h = blockIdx.y, b = blockIdx.z;
    const int tid = threadIdx.x, lane = tid & 31, warp = tid >> 5;
    const int lr = lane >> 2, lq = lane & 3;
    const int q0 = qt * 128;

    const size_t bh = (size_t)(b * Hh + h) * Ss;
    const float* Qg = Q + (bh + q0) * 64;
    const float* Kg = K + bh * 64;
    const float* Vg = V + bh * 64;

    uint32_t qf[8][4];
    {
        int r0 = warp * 16 + lr;
#pragma unroll
        for (int k8 = 0; k8 < 8; k8++) {
            int c = k8 * 8 + lq;
            qf[k8][0] = __float_as_uint(Qg[r0 * 64 + c]);
            qf[k8][1] = __float_as_uint(Qg[(r0 + 8) * 64 + c]);
            qf[k8][2] = __float_as_uint(Qg[r0 * 64 + c + 4]);
            qf[k8][3] = __float_as_uint(Qg[(r0 + 8) * 64 + c + 4]);
        }
    }

    float o[8][4];
#pragma unroll
    for (int dn = 0; dn < 8; dn++)
#pragma unroll
        for (int i = 0; i < 4; i++) o[dn][i] = 0.f;
    float m0 = -1e30f, m1 = -1e30f, l0 = 0.f, l1 = 0.f;

    const int lrow = tid >> 4;
    const int lcol = (tid & 15) << 2;

    auto issue_tile = [&](int jt, int buf) {
        const float* kb = Kg + (size_t)(jt * 64) * 64;
        const float* vb = Vg + (size_t)(jt * 64) * 64;
#pragma unroll
        for (int u = 0; u < 4; u++) {
            int r = lrow + 16 * u;
            cp16(&Ks[buf][r][lcol], kb + r * 64 + lcol);
            int g = r & 7;
            int slot = (r & ~7) | ((g & 1) ? ((g >> 1) + 4) : (g >> 1));
            cp16(&Vs[buf][slot][lcol], vb + r * 64 + lcol);
        }
        asm volatile("cp.async.commit_group;");
    };

    const int jmax = 2 * qt + 1;
    issue_tile(0, 0);

    for (int jt = 0; jt <= jmax; jt++) {
        const int cur = jt & 1;
        if (jt < jmax) {
            issue_tile(jt + 1, cur ^ 1);
            asm volatile("cp.async.wait_group 1;");
        } else {
            asm volatile("cp.async.wait_group 0;");
        }
        __syncthreads();

        float sc[8][4];
#pragma unroll
        for (int nt = 0; nt < 8; nt++)
#pragma unroll
            for (int i = 0; i < 4; i++) sc[nt][i] = 0.f;
#pragma unroll
        for (int k8 = 0; k8 < 8; k8++)
#pragma unroll
            for (int nt = 0; nt < 8; nt++)
                mma8(sc[nt], qf[k8],
                     Ks[cur][nt * 8 + lr][k8 * 8 + lq],
                     Ks[cur][nt * 8 + lr][k8 * 8 + lq + 4]);

        if (jt >= 2 * qt) {
            int r1 = q0 + warp * 16 + lr;
#pragma unroll
            for (int nt = 0; nt < 8; nt++) {
                int key = jt * 64 + nt * 8 + (lq << 1);
                if (key > r1) sc[nt][0] = -1e30f;
                if (key + 1 > r1) sc[nt][1] = -1e30f;
                if (key > r1 + 8) sc[nt][2] = -1e30f;
                if (key + 1 > r1 + 8) sc[nt][3] = -1e30f;
            }
        }

        float mx0 = -1e30f, mx1 = -1e30f;
#pragma unroll
        for (int nt = 0; nt < 8; nt++) {
            mx0 = fmaxf(mx0, fmaxf(sc[nt][0], sc[nt][1]));
            mx1 = fmaxf(mx1, fmaxf(sc[nt][2], sc[nt][3]));
        }
        mx0 = fmaxf(mx0, __shfl_xor_sync(0xffffffffu, mx0, 1));
        mx0 = fmaxf(mx0, __shfl_xor_sync(0xffffffffu, mx0, 2));
        mx1 = fmaxf(mx1, __shfl_xor_sync(0xffffffffu, mx1, 1));
        mx1 = fmaxf(mx1, __shfl_xor_sync(0xffffffffu, mx1, 2));
        float mn0 = fmaxf(m0, mx0), mn1 = fmaxf(m1, mx1);
        float fac0 = ex2(m0 - mn0), fac1 = ex2(m1 - mn1);

        float s0 = 0.f, s1 = 0.f;
#pragma unroll
        for (int nt = 0; nt < 8; nt++) {
            float p0 = ex2(sc[nt][0] - mn0);
            float p1 = ex2(sc[nt][1] - mn0);
            float p2 = ex2(sc[nt][2] - mn1);
            float p3 = ex2(sc[nt][3] - mn1);
            s0 += p0 + p1;
            s1 += p2 + p3;
            sc[nt][0] = f2tff(p0);
            sc[nt][1] = f2tff(p1);
            sc[nt][2] = f2tff(p2);
            sc[nt][3] = f2tff(p3);
        }
        s0 += __shfl_xor_sync(0xffffffffu, s0, 1);
        s0 += __shfl_xor_sync(0xffffffffu, s0, 2);
        s1 += __shfl_xor_sync(0xffffffffu, s1, 1);
        s1 += __shfl_xor_sync(0xffffffffu, s1, 2);
        l0 = l0 * fac0 + s0;
        l1 = l1 * fac1 + s1;
        m0 = mn0;
        m1 = mn1;
#pragma unroll
        for (int dn = 0; dn < 8; dn++) {
            o[dn][0] *= fac0; o[dn][1] *= fac0;
            o[dn][2] *= fac1; o[dn][3] *= fac1;
        }

#pragma unroll
        for (int k8 = 0; k8 < 8; k8++) {
            uint32_t af[4] = {__float_as_uint(sc[k8][0]), __float_as_uint(sc[k8][2]),
                              __float_as_uint(sc[k8][1]), __float_as_uint(sc[k8][3])};
#pragma unroll
            for (int dn = 0; dn < 8; dn++)
                mma8(o[dn], af,
                     Vs[cur][k8 * 8 + lq][dn * 8 + lr],
                     Vs[cur][k8 * 8 + lq + 4][dn * 8 + lr]);
        }
        __syncthreads();
    }

    // ---- epilogue: normalize + tf32, write PACKED aop[kc][row][36] ----
    float i0 = 1.0f / l0, i1 = 1.0f / l1;
    int grow = b * Ss + q0 + warp * 16 + lr;
#pragma unroll
    for (int dn = 0; dn < 8; dn++) {
        int e = dn * 8 + (lq << 1);           // d value, 0..62 even
        int kc = h * 2 + (e >> 5);            // global k = h*64+e, BK=32
        int ki = e & 31;
        float* p0 = AOP + ((size_t)kc * 4096 + grow) * 36 + ki;
        float* p1 = AOP + ((size_t)kc * 4096 + grow + 8) * 36 + ki;
        *(float2*)p0 = make_float2(f2tff(o[dn][0] * i0), f2tff(o[dn][1] * i0));
        *(float2*)p1 = make_float2(f2tff(o[dn][2] * i1), f2tff(o[dn][3] * i1));
    }
}

// ---------------------------------------------------------------------------
extern "C" void kernel_launch(void* const* d_in, const int* in_sizes, int n_in,
                              void* d_out, int out_size) {
    const float* x = (const float*)d_in[0];
    const float* w_qkv = (const float*)d_in[1];
    const float* w_out = (const float*)d_in[2];
    const float* freqs = (const float*)d_in[3];
    float* out = (float*)d_out;

    float *q, *k, *v, *xp, *wp, *wop, *aop, *cb, *sb;
    cudaGetSymbolAddress((void**)&q, g_q);
    cudaGetSymbolAddress((void**)&k, g_k);
    cudaGetSymbolAddress((void**)&v, g_v);
    cudaGetSymbolAddress((void**)&xp, g_xp);
    cudaGetSymbolAddress((void**)&wp, g_wp);
    cudaGetSymbolAddress((void**)&wop, g_wop);
    cudaGetSymbolAddress((void**)&aop, g_aop);
    cudaGetSymbolAddress((void**)&cb, g_cos);
    cudaGetSymbolAddress((void**)&sb, g_sin);

    cudaFuncSetAttribute(attn_kernel,
                         cudaFuncAttributeMaxDynamicSharedMemorySize,
                         ATTN_SMEM_BYTES);
    cudaFuncSetAttribute(gemm_qkv,
                         cudaFuncAttributeMaxDynamicSharedMemorySize,
                         GEMM_SMEM);
    cudaFuncSetAttribute(gemm_out,
                         cudaFuncAttributeMaxDynamicSharedMemorySize,
                         GEMM_SMEM);

    // 0) Pack operands + trig tables
    pack_a<<<(4096 * 1024) / 256, 256>>>(x, xp);
    pack_b<<<(1024 * 3072) / 256, 256>>>(w_qkv, wp, 3072);
    pack_b<<<(1024 * 1024) / 256, 256>>>(w_out, wop, 1024);
    trig_kernel<<<(Ss * DH) / 256, 256>>>(freqs, cb, sb);

    // 1) QKV projection + fused RoPE -> q/k/v in [b,h,s,d] (tf32)
    gemm_qkv<<<dim3(24, 32), 256, GEMM_SMEM>>>(xp, wp, q, k, v, cb, sb);
    // 2) Causal flash attention (writes packed aop)
    attn_kernel<<<dim3(Ss / 128, Hh, Bb), 256, ATTN_SMEM_BYTES>>>(q, k, v, aop);
    // 3) Output projection
    gemm_out<<<dim3(8, 32), 256, GEMM_SMEM>>>(aop, wop, out);
}

// round 12
// speedup vs baseline: 1.0134x; 1.0134x over previous
#include <cuda_runtime.h>
#include <cstdint>

// Problem constants
static constexpr int Bb = 2, Ss = 2048, Hh = 16, DH = 64, Dd = 1024;
static constexpr int KC32 = 32;                 // 1024 / 32 k-steps

// Scratch (static device globals — no allocations allowed)
__device__ float g_q[Bb * Hh * Ss * DH];        // rope'd, scaled(*log2e), tf32
__device__ float g_k[Bb * Hh * Ss * DH];
__device__ float g_v[Bb * Hh * Ss * DH];
__device__ float g_xp[32 * 4096 * 36];          // packed A gemm1 (tf32, pad 36)
__device__ float g_wp[32 * 24 * 4352];          // packed B w_qkv
__device__ float g_wop[32 * 8 * 4352];          // packed B w_out
__device__ float g_aop[32 * 4096 * 36];         // packed A gemm2 (attn out)
__device__ float g_cos[Ss * DH];                // cos(freqs)
__device__ float g_sin[Ss * DH];                // sin(freqs)

__device__ __forceinline__ uint32_t f2tf(float f) {
    uint32_t u;
    asm("cvt.rna.tf32.f32 %0, %1;" : "=r"(u) : "f"(f));
    return u;
}
__device__ __forceinline__ float f2tff(float f) { return __uint_as_float(f2tf(f)); }

__device__ __forceinline__ float ex2(float x) {
    float y;
    asm("ex2.approx.f32 %0, %1;" : "=f"(y) : "f"(x));
    return y;
}

__device__ __forceinline__ void cp16(void* smem_ptr, const void* gptr) {
    uint32_t sa = (uint32_t)__cvta_generic_to_shared(smem_ptr);
    asm volatile("cp.async.ca.shared.global [%0], [%1], 16;"
                 :: "r"(sa), "l"(gptr));
}

__device__ __forceinline__ void mma8(float (&c)[4], const uint32_t (&a)[4],
                                     uint32_t b0, uint32_t b1) {
    asm volatile(
        "mma.sync.aligned.m16n8k8.row.col.f32.tf32.tf32.f32 "
        "{%0,%1,%2,%3}, {%4,%5,%6,%7}, {%8,%9}, {%0,%1,%2,%3};"
        : "+f"(c[0]), "+f"(c[1]), "+f"(c[2]), "+f"(c[3])
        : "r"(a[0]), "r"(a[1]), "r"(a[2]), "r"(a[3]), "r"(b0), "r"(b1));
}

// ---- mbarrier + 1D bulk-copy helpers ----
__device__ __forceinline__ uint32_t s2u(const void* p) {
    return (uint32_t)__cvta_generic_to_shared(p);
}
__device__ __forceinline__ void mbar_init(uint32_t addr, uint32_t cnt) {
    asm volatile("mbarrier.init.shared.b64 [%0], %1;" :: "r"(addr), "r"(cnt));
}
__device__ __forceinline__ void mbar_expect_tx(uint32_t addr, uint32_t bytes) {
    asm volatile("mbarrier.arrive.expect_tx.shared.b64 _, [%0], %1;"
                 :: "r"(addr), "r"(bytes));
}
__device__ __forceinline__ void mbar_wait(uint32_t addr, uint32_t parity) {
    asm volatile(
        "{\n\t.reg .pred P;\n"
        "W%=:\n\t"
        "mbarrier.try_wait.parity.shared.b64 P, [%0], %1;\n\t"
        "@!P bra W%=;\n\t}"
        :: "r"(addr), "r"(parity) : "memory");
}
__device__ __forceinline__ void bulk_g2s(uint32_t dst, const void* src,
                                         uint32_t bytes, uint32_t mbar) {
    asm volatile(
        "cp.async.bulk.shared::cta.global.mbarrier::complete_tx::bytes "
        "[%0], [%1], %2, [%3];"
        :: "r"(dst), "l"(src), "r"(bytes), "r"(mbar) : "memory");
}

// ---------------------------------------------------------------------------
// Pack kernels: contiguous, padded, tf32-rounded tiles (BK=32 layouts).
// ---------------------------------------------------------------------------
__global__ __launch_bounds__(256) void pack_a(
    const float* __restrict__ X, float* __restrict__ Xp) {
    int idx = blockIdx.x * 256 + threadIdx.x;   // over 4096*1024
    int m = idx >> 10, k = idx & 1023;
    Xp[((size_t)(k >> 5) * 4096 + m) * 36 + (k & 31)] = f2tff(X[idx]);
}

__global__ __launch_bounds__(256) void pack_b(
    const float* __restrict__ W, float* __restrict__ Wp, int N) {
    int idx = blockIdx.x * 256 + threadIdx.x;   // over 1024*N
    int k = idx / N, n = idx - k * N;
    size_t chunk = (size_t)(k >> 5) * (N >> 7) + (n >> 7);
    Wp[chunk * 4352 + (k & 31) * 136 + (n & 127)] = f2tff(W[idx]);
}

// cos/sin tables for the fused-rope GEMM epilogue (precise sincosf, once).
__global__ __launch_bounds__(256) void trig_kernel(
    const float* __restrict__ freqs, float* __restrict__ cb,
    float* __restrict__ sb) {
    int i = blockIdx.x * 256 + threadIdx.x;     // 2048*64
    float s, c;
    sincosf(freqs[i], &s, &c);
    cb[i] = c;
    sb[i] = s;
}

// ---------------------------------------------------------------------------
// GEMM mainloop (R10 proven best): 256x128 tile, BK=32, 8 warps (4x2 of
// 64x64), 3-stage mbarrier + bulk-copy pipeline.
// ---------------------------------------------------------------------------
static constexpr int AST_W = 256 * 36;          // 9216 words
static constexpr int BST_W = 32 * 136;          // 4352 words
static constexpr int STG_W = AST_W + BST_W;     // 13568 words = 54272 B
static constexpr int GEMM_SMEM = 3 * STG_W * 4; // 162816 B

#define GEMM_MAINLOOP(ApPtr, BpPtr, NBv)                                      \
    extern __shared__ uint32_t gsm[];                                         \
    __shared__ uint64_t gmb[3];                                               \
    const int tid = threadIdx.x, lane = tid & 31, warp = tid >> 5;            \
    const int wm = (warp >> 1) * 64, wn = (warp & 1) * 64;                    \
    const int lr = lane >> 2, lq = lane & 3;                                  \
    const int bm = blockIdx.y * 256, nb = blockIdx.x;                         \
    const uint32_t mb0 = s2u(gmb);                                            \
    const uint32_t smem_base = s2u(gsm);                                      \
    if (tid == 0) {                                                           \
        mbar_init(mb0, 1);                                                    \
        mbar_init(mb0 + 8, 1);                                                \
        mbar_init(mb0 + 16, 1);                                               \
        asm volatile("fence.proxy.async.shared::cta;" ::: "memory");          \
    }                                                                         \
    __syncthreads();                                                          \
    auto issue = [&](int i) {                                                 \
        if (tid == 0) {                                                       \
            int st = i % 3;                                                   \
            uint32_t m = mb0 + st * 8;                                        \
            uint32_t dst = smem_base + st * (STG_W * 4);                      \
            mbar_expect_tx(m, STG_W * 4);                                     \
            bulk_g2s(dst, (ApPtr) + ((size_t)i * 4096 + bm) * 36,             \
                     AST_W * 4, m);                                           \
            bulk_g2s(dst + AST_W * 4, (BpPtr) + (size_t)(i * (NBv) + nb) *    \
                     BST_W, BST_W * 4, m);                                    \
        }                                                                     \
    };                                                                        \
    float acc[4][8][4];                                                       \
    _Pragma("unroll") for (int mt = 0; mt < 4; mt++)                          \
        _Pragma("unroll") for (int nt = 0; nt < 8; nt++)                      \
            _Pragma("unroll") for (int i = 0; i < 4; i++)                     \
                acc[mt][nt][i] = 0.f;                                         \
    issue(0);                                                                 \
    issue(1);                                                                 \
    issue(2);                                                                 \
    for (int i = 0; i < KC32; i++) {                                          \
        const int st = i % 3;                                                 \
        mbar_wait(mb0 + st * 8, (i / 3) & 1);                                 \
        const uint32_t* As = gsm + st * STG_W;                                \
        const uint32_t* Bs = As + AST_W;                                      \
        _Pragma("unroll") for (int ks = 0; ks < 32; ks += 8) {                \
            uint32_t a[4][4], b[8][2];                                        \
            _Pragma("unroll") for (int mt = 0; mt < 4; mt++) {                \
                int r0 = (wm + mt * 16 + lr) * 36, c0 = ks + lq;              \
                a[mt][0] = As[r0 + c0];                                       \
                a[mt][1] = As[r0 + 288 + c0];                                 \
                a[mt][2] = As[r0 + c0 + 4];                                   \
                a[mt][3] = As[r0 + 288 + c0 + 4];                             \
            }                                                                 \
            _Pragma("unroll") for (int nt = 0; nt < 8; nt++) {                \
                int cc = wn + nt * 8 + lr, kr = ks + lq;                      \
                b[nt][0] = Bs[kr * 136 + cc];                                 \
                b[nt][1] = Bs[(kr + 4) * 136 + cc];                           \
            }                                                                 \
            _Pragma("unroll") for (int mt = 0; mt < 4; mt++)                  \
                _Pragma("unroll") for (int nt = 0; nt < 8; nt++)              \
                    mma8(acc[mt][nt], a[mt], b[nt][0], b[nt][1]);             \
        }                                                                     \
        __syncthreads();                                                      \
        if (i + 3 < KC32) issue(i + 3);                                       \
    }

// ---------------------------------------------------------------------------
// GEMM 1: QKV projection with FUSED RoPE epilogue (R10 proven).
// ---------------------------------------------------------------------------
__global__ __launch_bounds__(256) void gemm_qkv(
    const float* __restrict__ Ap, const float* __restrict__ Bp,
    float* __restrict__ Qo, float* __restrict__ Ko, float* __restrict__ Vo,
    const float* __restrict__ cb, const float* __restrict__ sb) {
    GEMM_MAINLOOP(Ap, Bp, 24)

    const int col0 = nb * 128 + wn;             // 64-col slice start
    const int type = col0 >> 10;                // 0=q, 1=k, 2=v
    const int h = (col0 >> 6) & 15;
    const float qsc = 0.125f * 1.4426950408889634f;

    if (type < 2) {
        float* dst0 = (type == 0) ? Qo : Ko;
#pragma unroll
        for (int mt = 0; mt < 4; mt++) {
#pragma unroll
            for (int e2 = 0; e2 < 2; e2++) {
                int r = bm + wm + mt * 16 + lr + 8 * e2;
                int s = r & 2047, bb = r >> 11;
                float* dst = dst0 + ((size_t)(bb * Hh + h) * Ss + s) * 64;
                const float* cr = cb + s * 64;
                const float* sr = sb + s * 64;
#pragma unroll
                for (int nt = 0; nt < 4; nt++) {
                    int dlo = nt * 8 + (lq << 1);
                    float2 clo = *(const float2*)&cr[dlo];
                    float2 slo = *(const float2*)&sr[dlo];
                    float2 chi = *(const float2*)&cr[dlo + 32];
                    float2 shi = *(const float2*)&sr[dlo + 32];
                    float al0 = acc[mt][nt][2 * e2], al1 = acc[mt][nt][2 * e2 + 1];
                    float ah0 = acc[mt][nt + 4][2 * e2], ah1 = acc[mt][nt + 4][2 * e2 + 1];
                    float ol0 = al0 * clo.x - ah0 * slo.x;
                    float ol1 = al1 * clo.y - ah1 * slo.y;
                    float oh0 = ah0 * chi.x + al0 * shi.x;
                    float oh1 = ah1 * chi.y + al1 * shi.y;
                    if (type == 0) { ol0 *= qsc; ol1 *= qsc; oh0 *= qsc; oh1 *= qsc; }
                    *(float2*)&dst[dlo] = make_float2(f2tff(ol0), f2tff(ol1));
                    *(float2*)&dst[dlo + 32] = make_float2(f2tff(oh0), f2tff(oh1));
                }
            }
        }
    } else {
#pragma unroll
        for (int mt = 0; mt < 4; mt++) {
#pragma unroll
            for (int e2 = 0; e2 < 2; e2++) {
                int r = bm + wm + mt * 16 + lr + 8 * e2;
                int s = r & 2047, bb = r >> 11;
                float* dst = Vo + ((size_t)(bb * Hh + h) * Ss + s) * 64;
#pragma unroll
                for (int nt = 0; nt < 8; nt++) {
                    int d = nt * 8 + (lq << 1);
                    *(float2*)&dst[d] =
                        make_float2(f2tff(acc[mt][nt][2 * e2]),
                                    f2tff(acc[mt][nt][2 * e2 + 1]));
                }
            }
        }
    }
}

// ---------------------------------------------------------------------------
// GEMM 2: output projection, plain row-major epilogue.
// ---------------------------------------------------------------------------
__global__ __launch_bounds__(256) void gemm_out(
    const float* __restrict__ Ap, const float* __restrict__ Bp,
    float* __restrict__ C) {
    GEMM_MAINLOOP(Ap, Bp, 8)

#pragma unroll
    for (int mt = 0; mt < 4; mt++)
#pragma unroll
        for (int nt = 0; nt < 8; nt++) {
            int row = bm + wm + mt * 16 + lr;
            int col = (nb << 7) + wn + nt * 8 + (lq << 1);
            *(float2*)&C[(size_t)row * 1024 + col] =
                make_float2(acc[mt][nt][0], acc[mt][nt][1]);
            *(float2*)&C[(size_t)(row + 8) * 1024 + col] =
                make_float2(acc[mt][nt][2], acc[mt][nt][3]);
        }
}

// ---------------------------------------------------------------------------
// Causal flash attention (R6 core) + two changes:
//  - P fed to mma as raw fp32 (HW tf32 truncation) — 64 cvt/tile removed
//  - 2 CTAs/SM via launch_bounds(256,2)  (smem 71.7KB x2 = 143KB fits)
// ---------------------------------------------------------------------------
static constexpr int KS_WORDS = 64 * 68;
static constexpr int VS_WORDS = 64 * 72;
static constexpr int ATTN_SMEM_BYTES = (2 * KS_WORDS + 2 * VS_WORDS) * 4;  // 71680

__global__ __launch_bounds__(256, 2) void attn_kernel(
    const float* __restrict__ Q, const float* __restrict__ K,
    const float* __restrict__ V, float* __restrict__ AOP) {
    extern __shared__ uint32_t dynsmem[];
    uint32_t (*Ks)[64][68] = reinterpret_cast<uint32_t (*)[64][68]>(dynsmem);
    uint32_t (*Vs)[64][72] =
        reinterpret_cast<uint32_t (*)[64][72]>(dynsmem + 2 * KS_WORDS);

    const int qt = gridDim.x - 1 - blockIdx.x;
    const int h = blockIdx.y, b = blockIdx.z;
    const int tid = threadIdx.x, lane = tid & 31, warp = tid >> 5;
    const int lr = lane >> 2, lq = lane & 3;
    const int q0 = qt * 128;

    const size_t bh = (size_t)(b * Hh + h) * Ss;
    const float* Qg = Q + (bh + q0) * 64;
    const float* Kg = K + bh * 64;
    const float* Vg = V + bh * 64;

    uint32_t qf[8][4];
    {
        int r0 = warp * 16 + lr;
#pragma unroll
        for (int k8 = 0; k8 < 8; k8++) {
            int c = k8 * 8 + lq;
            qf[k8][0] = __float_as_uint(Qg[r0 * 64 + c]);
            qf[k8][1] = __float_as_uint(Qg[(r0 + 8) * 64 + c]);
            qf[k8][2] = __float_as_uint(Qg[r0 * 64 + c + 4]);
            qf[k8][3] = __float_as_uint(Qg[(r0 + 8) * 64 + c + 4]);
        }
    }

    float o[8][4];
#pragma unroll
    for (int dn = 0; dn < 8; dn++)
#pragma unroll
        for (int i = 0; i < 4; i++) o[dn][i] = 0.f;
    float m0 = -1e30f, m1 = -1e30f, l0 = 0.f, l1 = 0.f;

    const int lrow = tid >> 4;
    const int lcol = (tid & 15) << 2;

    auto issue_tile = [&](int jt, int buf) {
        const float* kb = Kg + (size_t)(jt * 64) * 64;
        const float* vb = Vg + (size_t)(jt * 64) * 64;
#pragma unroll
        for (int u = 0; u < 4; u++) {
            int r = lrow + 16 * u;
            cp16(&Ks[buf][r][lcol], kb + r * 64 + lcol);
            int g = r & 7;
            int slot = (r & ~7) | ((g & 1) ? ((g >> 1) + 4) : (g >> 1));
            cp16(&Vs[buf][slot][lcol], vb + r * 64 + lcol);
        }
        asm volatile("cp.async.commit_group;");
    };

    const int jmax = 2 * qt + 1;
    issue_tile(0, 0);

    for (int jt = 0; jt <= jmax; jt++) {
        const int cur = jt & 1;
        if (jt < jmax) {
            issue_tile(jt + 1, cur ^ 1);
            asm volatile("cp.async.wait_group 1;");
        } else {
            asm volatile("cp.async.wait_group 0;");
        }
        __syncthreads();

        float sc[8][4];
#pragma unroll
        for (int nt = 0; nt < 8; nt++)
#pragma unroll
            for (int i = 0; i < 4; i++) sc[nt][i] = 0.f;
#pragma unroll
        for (int k8 = 0; k8 < 8; k8++)
#pragma unroll
            for (int nt = 0; nt < 8; nt++)
                mma8(sc[nt], qf[k8],
                     Ks[cur][nt * 8 + lr][k8 * 8 + lq],
                     Ks[cur][nt * 8 + lr][k8 * 8 + lq + 4]);

        if (jt >= 2 * qt) {
            int r1 = q0 + warp * 16 + lr;
#pragma unroll
            for (int nt = 0; nt < 8; nt++) {
                int key = jt * 64 + nt * 8 + (lq << 1);
                if (key > r1) sc[nt][0] = -1e30f;
                if (key + 1 > r1) sc[nt][1] = -1e30f;
                if (key > r1 + 8) sc[nt][2] = -1e30f;
                if (key + 1 > r1 + 8) sc[nt][3] = -1e30f;
            }
        }

        float mx0 = -1e30f, mx1 = -1e30f;
#pragma unroll
        for (int nt = 0; nt < 8; nt++) {
            mx0 = fmaxf(mx0, fmaxf(sc[nt][0], sc[nt][1]));
            mx1 = fmaxf(mx1, fmaxf(sc[nt][2], sc[nt][3]));
        }
        mx0 = fmaxf(mx0, __shfl_xor_sync(0xffffffffu, mx0, 1));
        mx0 = fmaxf(mx0, __shfl_xor_sync(0xffffffffu, mx0, 2));
        mx1 = fmaxf(mx1, __shfl_xor_sync(0xffffffffu, mx1, 1));
        mx1 = fmaxf(mx1, __shfl_xor_sync(0xffffffffu, mx1, 2));
        float mn0 = fmaxf(m0, mx0), mn1 = fmaxf(m1, mx1);
        float fac0 = ex2(m0 - mn0), fac1 = ex2(m1 - mn1);

        float s0 = 0.f, s1 = 0.f;
#pragma unroll
        for (int nt = 0; nt < 8; nt++) {
            float p0 = ex2(sc[nt][0] - mn0);
            float p1 = ex2(sc[nt][1] - mn0);
            float p2 = ex2(sc[nt][2] - mn1);
            float p3 = ex2(sc[nt][3] - mn1);
            s0 += p0 + p1;
            s1 += p2 + p3;
            sc[nt][0] = p0;     // raw fp32 -> mma (HW tf32 truncation)
            sc[nt][1] = p1;
            sc[nt][2] = p2;
            sc[nt][3] = p3;
        }
        s0 += __shfl_xor_sync(0xffffffffu, s0, 1);
        s0 += __shfl_xor_sync(0xffffffffu, s0, 2);
        s1 += __shfl_xor_sync(0xffffffffu, s1, 1);
        s1 += __shfl_xor_sync(0xffffffffu, s1, 2);
        l0 = l0 * fac0 + s0;
        l1 = l1 * fac1 + s1;
        m0 = mn0;
        m1 = mn1;
#pragma unroll
        for (int dn = 0; dn < 8; dn++) {
            o[dn][0] *= fac0; o[dn][1] *= fac0;
            o[dn][2] *= fac1; o[dn][3] *= fac1;
        }

#pragma unroll
        for (int k8 = 0; k8 < 8; k8++) {
            uint32_t af[4] = {__float_as_uint(sc[k8][0]), __float_as_uint(sc[k8][2]),
                              __float_as_uint(sc[k8][1]), __float_as_uint(sc[k8][3])};
#pragma unroll
            for (int dn = 0; dn < 8; dn++)
                mma8(o[dn], af,
                     Vs[cur][k8 * 8 + lq][dn * 8 + lr],
                     Vs[cur][k8 * 8 + lq + 4][dn * 8 + lr]);
        }
        __syncthreads();
    }

    // ---- epilogue: normalize + tf32, write PACKED aop[kc][row][36] ----
    float i0 = 1.0f / l0, i1 = 1.0f / l1;
    int grow = b * Ss + q0 + warp * 16 + lr;
#pragma unroll
    for (int dn = 0; dn < 8; dn++) {
        int e = dn * 8 + (lq << 1);           // d value, 0..62 even
        int kc = h * 2 + (e >> 5);            // global k = h*64+e, BK=32
        int ki = e & 31;
        float* p0 = AOP + ((size_t)kc * 4096 + grow) * 36 + ki;
        float* p1 = AOP + ((size_t)kc * 4096 + grow + 8) * 36 + ki;
        *(float2*)p0 = make_float2(f2tff(o[dn][0] * i0), f2tff(o[dn][1] * i0));
        *(float2*)p1 = make_float2(f2tff(o[dn][2] * i1), f2tff(o[dn][3] * i1));
    }
}

// ---------------------------------------------------------------------------
extern "C" void kernel_launch(void* const* d_in, const int* in_sizes, int n_in,
                              void* d_out, int out_size) {
    const float* x = (const float*)d_in[0];
    const float* w_qkv = (const float*)d_in[1];
    const float* w_out = (const float*)d_in[2];
    const float* freqs = (const float*)d_in[3];
    float* out = (float*)d_out;

    float *q, *k, *v, *xp, *wp, *wop, *aop, *cb, *sb;
    cudaGetSymbolAddress((void**)&q, g_q);
    cudaGetSymbolAddress((void**)&k, g_k);
    cudaGetSymbolAddress((void**)&v, g_v);
    cudaGetSymbolAddress((void**)&xp, g_xp);
    cudaGetSymbolAddress((void**)&wp, g_wp);
    cudaGetSymbolAddress((void**)&wop, g_wop);
    cudaGetSymbolAddress((void**)&aop, g_aop);
    cudaGetSymbolAddress((void**)&cb, g_cos);
    cudaGetSymbolAddress((void**)&sb, g_sin);

    cudaFuncSetAttribute(attn_kernel,
                         cudaFuncAttributeMaxDynamicSharedMemorySize,
                         ATTN_SMEM_BYTES);
    cudaFuncSetAttribute(gemm_qkv,
                         cudaFuncAttributeMaxDynamicSharedMemorySize,
                         GEMM_SMEM);
    cudaFuncSetAttribute(gemm_out,
                         cudaFuncAttributeMaxDynamicSharedMemorySize,
                         GEMM_SMEM);

    // 0) Pack operands + trig tables
    pack_a<<<(4096 * 1024) / 256, 256>>>(x, xp);
    pack_b<<<(1024 * 3072) / 256, 256>>>(w_qkv, wp, 3072);
    pack_b<<<(1024 * 1024) / 256, 256>>>(w_out, wop, 1024);
    trig_kernel<<<(Ss * DH) / 256, 256>>>(freqs, cb, sb);

    // 1) QKV projection + fused RoPE -> q/k/v in [b,h,s,d] (tf32)
    gemm_qkv<<<dim3(24, 16), 256, GEMM_SMEM>>>(xp, wp, q, k, v, cb, sb);
    // 2) Causal flash attention (writes packed aop)
    attn_kernel<<<dim3(Ss / 128, Hh, Bb), 256, ATTN_SMEM_BYTES>>>(q, k, v, aop);
    // 3) Output projection
    gemm_out<<<dim3(8, 16), 256, GEMM_SMEM>>>(aop, wop, out);
}

// round 14
// speedup vs baseline: 1.0339x; 1.0203x over previous
#include <cuda_runtime.h>
#include <cstdint>

// Problem constants
static constexpr int Bb = 2, Ss = 2048, Hh = 16, DH = 64, Dd = 1024;
static constexpr int KC32 = 32;                 // 1024 / 32 k-steps

// Scratch (static device globals — no allocations allowed)
__device__ float g_q[Bb * Hh * Ss * DH];        // rope'd, scaled(*log2e), tf32
__device__ float g_k[Bb * Hh * Ss * DH];
__device__ float g_v[Bb * Hh * Ss * DH];
__device__ float g_xp[32 * 4096 * 32];          // frag-packed A gemm1
__device__ float g_wp[32 * 24 * 4096];          // frag-packed B w_qkv
__device__ float g_wop[32 * 8 * 4096];          // frag-packed B w_out
__device__ float g_aop[32 * 4096 * 32];         // frag-packed A gemm2
__device__ float g_cos[Ss * DH];                // cos(freqs)
__device__ float g_sin[Ss * DH];                // sin(freqs)

__device__ __forceinline__ uint32_t f2tf(float f) {
    uint32_t u;
    asm("cvt.rna.tf32.f32 %0, %1;" : "=r"(u) : "f"(f));
    return u;
}
__device__ __forceinline__ float f2tff(float f) { return __uint_as_float(f2tf(f)); }

__device__ __forceinline__ float ex2(float x) {
    float y;
    asm("ex2.approx.f32 %0, %1;" : "=f"(y) : "f"(x));
    return y;
}

__device__ __forceinline__ void cp16(void* smem_ptr, const void* gptr) {
    uint32_t sa = (uint32_t)__cvta_generic_to_shared(smem_ptr);
    asm volatile("cp.async.ca.shared.global [%0], [%1], 16;"
                 :: "r"(sa), "l"(gptr));
}

__device__ __forceinline__ void mma8(float (&c)[4], const uint32_t (&a)[4],
                                     uint32_t b0, uint32_t b1) {
    asm volatile(
        "mma.sync.aligned.m16n8k8.row.col.f32.tf32.tf32.f32 "
        "{%0,%1,%2,%3}, {%4,%5,%6,%7}, {%8,%9}, {%0,%1,%2,%3};"
        : "+f"(c[0]), "+f"(c[1]), "+f"(c[2]), "+f"(c[3])
        : "r"(a[0]), "r"(a[1]), "r"(a[2]), "r"(a[3]), "r"(b0), "r"(b1));
}

// ---- mbarrier + 1D bulk-copy helpers ----
__device__ __forceinline__ uint32_t s2u(const void* p) {
    return (uint32_t)__cvta_generic_to_shared(p);
}
__device__ __forceinline__ void mbar_init(uint32_t addr, uint32_t cnt) {
    asm volatile("mbarrier.init.shared.b64 [%0], %1;" :: "r"(addr), "r"(cnt));
}
__device__ __forceinline__ void mbar_expect_tx(uint32_t addr, uint32_t bytes) {
    asm volatile("mbarrier.arrive.expect_tx.shared.b64 _, [%0], %1;"
                 :: "r"(addr), "r"(bytes));
}
__device__ __forceinline__ void mbar_wait(uint32_t addr, uint32_t parity) {
    asm volatile(
        "{\n\t.reg .pred P;\n"
        "W%=:\n\t"
        "mbarrier.try_wait.parity.shared.b64 P, [%0], %1;\n\t"
        "@!P bra W%=;\n\t}"
        :: "r"(addr), "r"(parity) : "memory");
}
__device__ __forceinline__ void bulk_g2s(uint32_t dst, const void* src,
                                         uint32_t bytes, uint32_t mbar) {
    asm volatile(
        "cp.async.bulk.shared::cta.global.mbarrier::complete_tx::bytes "
        "[%0], [%1], %2, [%3];"
        :: "r"(dst), "l"(src), "r"(bytes), "r"(mbar) : "memory");
}

// ---------------------------------------------------------------------------
// Fragment-packed A layout (per k-chunk kc, per 256-row m-block mb):
//   region (kc*16+mb)*8192 floats; quad for (wm4, mt, ks8, lane) at
//   ((wm4*16 + mt*4 + ks8)*32 + lane)*4 = [A(r,c), A(r+8,c), A(r,c+4), A(r+8,c+4)]
//   r = mb*256 + wm4*64 + mt*16 + (lane>>2), c = kc*32 + ks8*8 + (lane&3)
// ---------------------------------------------------------------------------
__global__ __launch_bounds__(256) void pack_a(
    const float* __restrict__ X, float* __restrict__ Xp) {
    int idx = blockIdx.x * 256 + threadIdx.x;   // 1M quads
    int lane = idx & 31;
    int ks8 = (idx >> 5) & 3;
    int mt = (idx >> 7) & 3;
    int wm4 = (idx >> 9) & 3;
    int mb = (idx >> 11) & 15;
    int kc = idx >> 15;
    int row = mb * 256 + wm4 * 64 + mt * 16 + (lane >> 2);
    int c = kc * 32 + ks8 * 8 + (lane & 3);
    const float* xr = X + (size_t)row * 1024 + c;
    float4 q = make_float4(f2tff(xr[0]), f2tff(xr[8192]),      // +8 rows
                           f2tff(xr[4]), f2tff(xr[8196]));
    *(float4*)&Xp[(size_t)idx * 4] = q;
}

// Fragment-packed B layout (per kc, per 128-col n-block nb):
//   region (kc*NB+nb)*4096 floats; pair for (wn2, nt, ks8, lane) at
//   ((wn2*32 + nt*4 + ks8)*32 + lane)*2 = [B(k,c), B(k+4,c)]
//   c = nb*128 + wn2*64 + nt*8 + (lane>>2), k = kc*32 + ks8*8 + (lane&3)
// ---------------------------------------------------------------------------
__global__ __launch_bounds__(256) void pack_b(
    const float* __restrict__ W, float* __restrict__ Wp, int N) {
    int idx = blockIdx.x * 256 + threadIdx.x;
    int NB = N >> 7;
    int per_kc = NB << 11;
    int kc = idx / per_kc;
    int rem = idx - kc * per_kc;
    int nb = rem >> 11;
    int w = rem & 2047;
    int lane = w & 31;
    int ks8 = (w >> 5) & 3;
    int nt = (w >> 7) & 7;
    int wn2 = (w >> 10) & 1;
    int col = nb * 128 + wn2 * 64 + nt * 8 + (lane >> 2);
    int k0 = kc * 32 + ks8 * 8 + (lane & 3);
    const float* wr = W + (size_t)k0 * N + col;
    *(float2*)&Wp[(size_t)idx * 2] =
        make_float2(f2tff(wr[0]), f2tff(wr[4 * N]));
}

// cos/sin tables for the fused-rope GEMM epilogue (precise sincosf, once).
__global__ __launch_bounds__(256) void trig_kernel(
    const float* __restrict__ freqs, float* __restrict__ cb,
    float* __restrict__ sb) {
    int i = blockIdx.x * 256 + threadIdx.x;     // 2048*64
    float s, c;
    sincosf(freqs[i], &s, &c);
    cb[i] = c;
    sb[i] = s;
}

// ---------------------------------------------------------------------------
// GEMM mainloop: 256x128 tile, BK=32, 8 warps (4x2 of 64x64), 3-stage
// mbarrier + bulk pipeline, FRAGMENT-PACKED smem (LDS.128/LDS.64 loads).
// ---------------------------------------------------------------------------
static constexpr int AST_W = 256 * 32;          // 8192 words
static constexpr int BST_W = 32 * 128;          // 4096 words
static constexpr int STG_W = AST_W + BST_W;     // 12288 words = 49152 B
static constexpr int GEMM_SMEM = 3 * STG_W * 4; // 147456 B

#define GEMM_MAINLOOP(ApPtr, BpPtr, NBv)                                      \
    extern __shared__ uint32_t gsm[];                                         \
    __shared__ uint64_t gmb[3];                                               \
    const int tid = threadIdx.x, lane = tid & 31, warp = tid >> 5;            \
    const int wm = (warp >> 1) * 64, wn = (warp & 1) * 64;                    \
    const int warpm = warp >> 1, wn2 = warp & 1;                              \
    const int lr = lane >> 2, lq = lane & 3;                                  \
    const int bm = blockIdx.y * 256, nb = blockIdx.x;                         \
    const uint32_t mb0 = s2u(gmb);                                            \
    const uint32_t smem_base = s2u(gsm);                                      \
    if (tid == 0) {                                                           \
        mbar_init(mb0, 1);                                                    \
        mbar_init(mb0 + 8, 1);                                                \
        mbar_init(mb0 + 16, 1);                                               \
        asm volatile("fence.proxy.async.shared::cta;" ::: "memory");          \
    }                                                                         \
    __syncthreads();                                                          \
    auto issue = [&](int i) {                                                 \
        if (tid == 0) {                                                       \
            int st = i % 3;                                                   \
            uint32_t m = mb0 + st * 8;                                        \
            uint32_t dst = smem_base + st * (STG_W * 4);                      \
            mbar_expect_tx(m, STG_W * 4);                                     \
            bulk_g2s(dst, (ApPtr) + (size_t)(i * 16 + blockIdx.y) * 8192,     \
                     AST_W * 4, m);                                           \
            bulk_g2s(dst + AST_W * 4, (BpPtr) + (size_t)(i * (NBv) + nb) *    \
                     4096, BST_W * 4, m);                                     \
        }                                                                     \
    };                                                                        \
    float acc[4][8][4];                                                       \
    _Pragma("unroll") for (int mt = 0; mt < 4; mt++)                          \
        _Pragma("unroll") for (int nt = 0; nt < 8; nt++)                      \
            _Pragma("unroll") for (int i = 0; i < 4; i++)                     \
                acc[mt][nt][i] = 0.f;                                         \
    issue(0);                                                                 \
    issue(1);                                                                 \
    issue(2);                                                                 \
    for (int i = 0; i < KC32; i++) {                                          \
        const int st = i % 3;                                                 \
        mbar_wait(mb0 + st * 8, (i / 3) & 1);                                 \
        const uint32_t* As = gsm + st * STG_W;                                \
        const uint32_t* Bs = As + AST_W;                                      \
        _Pragma("unroll") for (int ks8 = 0; ks8 < 4; ks8++) {                 \
            uint32_t a[4][4], b[8][2];                                        \
            _Pragma("unroll") for (int mt = 0; mt < 4; mt++) {                \
                uint4 av = *(const uint4*)&As[                                \
                    ((warpm * 16 + mt * 4 + ks8) * 32 + lane) * 4];           \
                a[mt][0] = av.x; a[mt][1] = av.y;                             \
                a[mt][2] = av.z; a[mt][3] = av.w;                             \
            }                                                                 \
            _Pragma("unroll") for (int nt = 0; nt < 8; nt++) {                \
                uint2 bv = *(const uint2*)&Bs[                                \
                    ((wn2 * 32 + nt * 4 + ks8) * 32 + lane) * 2];             \
                b[nt][0] = bv.x; b[nt][1] = bv.y;                             \
            }                                                                 \
            _Pragma("unroll") for (int mt = 0; mt < 4; mt++)                  \
                _Pragma("unroll") for (int nt = 0; nt < 8; nt++)              \
                    mma8(acc[mt][nt], a[mt], b[nt][0], b[nt][1]);             \
        }                                                                     \
        __syncthreads();                                                      \
        if (i + 3 < KC32) issue(i + 3);                                       \
    }

// ---------------------------------------------------------------------------
// GEMM 1: QKV projection with FUSED RoPE epilogue (R10 proven mapping).
// ---------------------------------------------------------------------------
__global__ __launch_bounds__(256) void gemm_qkv(
    const float* __restrict__ Ap, const float* __restrict__ Bp,
    float* __restrict__ Qo, float* __restrict__ Ko, float* __restrict__ Vo,
    const float* __restrict__ cb, const float* __restrict__ sb) {
    GEMM_MAINLOOP(Ap, Bp, 24)

    const int col0 = nb * 128 + wn;             // 64-col slice start
    const int type = col0 >> 10;                // 0=q, 1=k, 2=v
    const int h = (col0 >> 6) & 15;
    const float qsc = 0.125f * 1.4426950408889634f;

    if (type < 2) {
        float* dst0 = (type == 0) ? Qo : Ko;
#pragma unroll
        for (int mt = 0; mt < 4; mt++) {
#pragma unroll
            for (int e2 = 0; e2 < 2; e2++) {
                int r = bm + wm + mt * 16 + lr + 8 * e2;
                int s = r & 2047, bbx = r >> 11;
                float* dst = dst0 + ((size_t)(bbx * Hh + h) * Ss + s) * 64;
                const float* cr = cb + s * 64;
                const float* sr = sb + s * 64;
#pragma unroll
                for (int nt = 0; nt < 4; nt++) {
                    int dlo = nt * 8 + (lq << 1);
                    float2 clo = *(const float2*)&cr[dlo];
                    float2 slo = *(const float2*)&sr[dlo];
                    float2 chi = *(const float2*)&cr[dlo + 32];
                    float2 shi = *(const float2*)&sr[dlo + 32];
                    float al0 = acc[mt][nt][2 * e2], al1 = acc[mt][nt][2 * e2 + 1];
                    float ah0 = acc[mt][nt + 4][2 * e2], ah1 = acc[mt][nt + 4][2 * e2 + 1];
                    float ol0 = al0 * clo.x - ah0 * slo.x;
                    float ol1 = al1 * clo.y - ah1 * slo.y;
                    float oh0 = ah0 * chi.x + al0 * shi.x;
                    float oh1 = ah1 * chi.y + al1 * shi.y;
                    if (type == 0) { ol0 *= qsc; ol1 *= qsc; oh0 *= qsc; oh1 *= qsc; }
                    *(float2*)&dst[dlo] = make_float2(f2tff(ol0), f2tff(ol1));
                    *(float2*)&dst[dlo + 32] = make_float2(f2tff(oh0), f2tff(oh1));
                }
            }
        }
    } else {
#pragma unroll
        for (int mt = 0; mt < 4; mt++) {
#pragma unroll
            for (int e2 = 0; e2 < 2; e2++) {
                int r = bm + wm + mt * 16 + lr + 8 * e2;
                int s = r & 2047, bbx = r >> 11;
                float* dst = Vo + ((size_t)(bbx * Hh + h) * Ss + s) * 64;
#pragma unroll
                for (int nt = 0; nt < 8; nt++) {
                    int d = nt * 8 + (lq << 1);
                    *(float2*)&dst[d] =
                        make_float2(f2tff(acc[mt][nt][2 * e2]),
                                    f2tff(acc[mt][nt][2 * e2 + 1]));
                }
            }
        }
    }
}

// ---------------------------------------------------------------------------
// GEMM 2: output projection, plain row-major epilogue.
// ---------------------------------------------------------------------------
__global__ __launch_bounds__(256) void gemm_out(
    const float* __restrict__ Ap, const float* __restrict__ Bp,
    float* __restrict__ C) {
    GEMM_MAINLOOP(Ap, Bp, 8)

#pragma unroll
    for (int mt = 0; mt < 4; mt++)
#pragma unroll
        for (int nt = 0; nt < 8; nt++) {
            int row = bm + wm + mt * 16 + lr;
            int col = (nb << 7) + wn + nt * 8 + (lq << 1);
            *(float2*)&C[(size_t)row * 1024 + col] =
                make_float2(acc[mt][nt][0], acc[mt][nt][1]);
            *(float2*)&C[(size_t)(row + 8) * 1024 + col] =
                make_float2(acc[mt][nt][2], acc[mt][nt][3]);
        }
}

// ---------------------------------------------------------------------------
// Causal flash attention (R12 best config). Epilogue writes FRAGMENT-PACKED
// A tiles for gemm2 (scattered STG.32, addresses per packed-A layout).
// ---------------------------------------------------------------------------
static constexpr int KS_WORDS = 64 * 68;
static constexpr int VS_WORDS = 64 * 72;
static constexpr int ATTN_SMEM_BYTES = (2 * KS_WORDS + 2 * VS_WORDS) * 4;  // 71680

__global__ __launch_bounds__(256, 2) void attn_kernel(
    const float* __restrict__ Q, const float* __restrict__ K,
    const float* __restrict__ V, float* __restrict__ AOP) {
    extern __shared__ uint32_t dynsmem[];
    uint32_t (*Ks)[64][68] = reinterpret_cast<uint32_t (*)[64][68]>(dynsmem);
    uint32_t (*Vs)[64][72] =
        reinterpret_cast<uint32_t (*)[64][72]>(dynsmem + 2 * KS_WORDS);

    const int qt = gridDim.x - 1 - blockIdx.x;
    const int h = blockIdx.y, b = blockIdx.z;
    const int tid = threadIdx.x, lane = tid & 31, warp = tid >> 5;
    const int lr = lane >> 2, lq = lane & 3;
    const int q0 = qt * 128;

    const size_t bh = (size_t)(b * Hh + h) * Ss;
    const float* Qg = Q + (bh + q0) * 64;
    const float* Kg = K + bh * 64;
    const float* Vg = V + bh * 64;

    uint32_t qf[8][4];
    {
        int r0 = warp * 16 + lr;
#pragma unroll
        for (int k8 = 0; k8 < 8; k8++) {
            int c = k8 * 8 + lq;
            qf[k8][0] = __float_as_uint(Qg[r0 * 64 + c]);
            qf[k8][1] = __float_as_uint(Qg[(r0 + 8) * 64 + c]);
            qf[k8][2] = __float_as_uint(Qg[r0 * 64 + c + 4]);
            qf[k8][3] = __float_as_uint(Qg[(r0 + 8) * 64 + c + 4]);
        }
    }

    float o[8][4];
#pragma unroll
    for (int dn = 0; dn < 8; dn++)
#pragma unroll
        for (int i = 0; i < 4; i++) o[dn][i] = 0.f;
    float m0 = -1e30f, m1 = -1e30f, l0 = 0.f, l1 = 0.f;

    const int lrow = tid >> 4;
    const int lcol = (tid & 15) << 2;

    auto issue_tile = [&](int jt, int buf) {
        const float* kb = Kg + (size_t)(jt * 64) * 64;
        const float* vb = Vg + (size_t)(jt * 64) * 64;
#pragma unroll
        for (int u = 0; u < 4; u++) {
            int r = lrow + 16 * u;
            cp16(&Ks[buf][r][lcol], kb + r * 64 + lcol);
            int g = r & 7;
            int slot = (r & ~7) | ((g & 1) ? ((g >> 1) + 4) : (g >> 1));
            cp16(&Vs[buf][slot][lcol], vb + r * 64 + lcol);
        }
        asm volatile("cp.async.commit_group;");
    };

    const int jmax = 2 * qt + 1;
    issue_tile(0, 0);

    for (int jt = 0; jt <= jmax; jt++) {
        const int cur = jt & 1;
        if (jt < jmax) {
            issue_tile(jt + 1, cur ^ 1);
            asm volatile("cp.async.wait_group 1;");
        } else {
            asm volatile("cp.async.wait_group 0;");
        }
        __syncthreads();

        float sc[8][4];
#pragma unroll
        for (int nt = 0; nt < 8; nt++)
#pragma unroll
            for (int i = 0; i < 4; i++) sc[nt][i] = 0.f;
#pragma unroll
        for (int k8 = 0; k8 < 8; k8++)
#pragma unroll
            for (int nt = 0; nt < 8; nt++)
                mma8(sc[nt], qf[k8],
                     Ks[cur][nt * 8 + lr][k8 * 8 + lq],
                     Ks[cur][nt * 8 + lr][k8 * 8 + lq + 4]);

        if (jt >= 2 * qt) {
            int r1 = q0 + warp * 16 + lr;
#pragma unroll
            for (int nt = 0; nt < 8; nt++) {
                int key = jt * 64 + nt * 8 + (lq << 1);
                if (key > r1) sc[nt][0] = -1e30f;
                if (key + 1 > r1) sc[nt][1] = -1e30f;
                if (key > r1 + 8) sc[nt][2] = -1e30f;
                if (key + 1 > r1 + 8) sc[nt][3] = -1e30f;
            }
        }

        float mx0 = -1e30f, mx1 = -1e30f;
#pragma unroll
        for (int nt = 0; nt < 8; nt++) {
            mx0 = fmaxf(mx0, fmaxf(sc[nt][0], sc[nt][1]));
            mx1 = fmaxf(mx1, fmaxf(sc[nt][2], sc[nt][3]));
        }
        mx0 = fmaxf(mx0, __shfl_xor_sync(0xffffffffu, mx0, 1));
        mx0 = fmaxf(mx0, __shfl_xor_sync(0xffffffffu, mx0, 2));
        mx1 = fmaxf(mx1, __shfl_xor_sync(0xffffffffu, mx1, 1));
        mx1 = fmaxf(mx1, __shfl_xor_sync(0xffffffffu, mx1, 2));
        float mn0 = fmaxf(m0, mx0), mn1 = fmaxf(m1, mx1);
        float fac0 = ex2(m0 - mn0), fac1 = ex2(m1 - mn1);

        float s0 = 0.f, s1 = 0.f;
#pragma unroll
        for (int nt = 0; nt < 8; nt++) {
            float p0 = ex2(sc[nt][0] - mn0);
            float p1 = ex2(sc[nt][1] - mn0);
            float p2 = ex2(sc[nt][2] - mn1);
            float p3 = ex2(sc[nt][3] - mn1);
            s0 += p0 + p1;
            s1 += p2 + p3;
            sc[nt][0] = p0;     // raw fp32 -> mma (HW tf32 truncation)
            sc[nt][1] = p1;
            sc[nt][2] = p2;
            sc[nt][3] = p3;
        }
        s0 += __shfl_xor_sync(0xffffffffu, s0, 1);
        s0 += __shfl_xor_sync(0xffffffffu, s0, 2);
        s1 += __shfl_xor_sync(0xffffffffu, s1, 1);
        s1 += __shfl_xor_sync(0xffffffffu, s1, 2);
        l0 = l0 * fac0 + s0;
        l1 = l1 * fac1 + s1;
        m0 = mn0;
        m1 = mn1;
#pragma unroll
        for (int dn = 0; dn < 8; dn++) {
            o[dn][0] *= fac0; o[dn][1] *= fac0;
            o[dn][2] *= fac1; o[dn][3] *= fac1;
        }

#pragma unroll
        for (int k8 = 0; k8 < 8; k8++) {
            uint32_t af[4] = {__float_as_uint(sc[k8][0]), __float_as_uint(sc[k8][2]),
                              __float_as_uint(sc[k8][1]), __float_as_uint(sc[k8][3])};
#pragma unroll
            for (int dn = 0; dn < 8; dn++)
                mma8(o[dn], af,
                     Vs[cur][k8 * 8 + lq][dn * 8 + lr],
                     Vs[cur][k8 * 8 + lq + 4][dn * 8 + lr]);
        }
        __syncthreads();
    }

    // ---- epilogue: normalize + tf32, write FRAGMENT-PACKED aop ----
    float i0 = 1.0f / l0, i1 = 1.0f / l1;
    int grow = b * Ss + q0 + warp * 16 + lr;

    auto paddr = [](int row, int c) -> size_t {
        int kc = c >> 5;
        int mb = row >> 8;
        int wm4 = (row >> 6) & 3;
        int mt = (row >> 4) & 3;
        int lane2 = ((row & 7) << 2) | (c & 3);
        int r = (((c >> 2) & 1) << 1) | ((row >> 3) & 1);
        int ks8 = (c >> 3) & 3;
        return (size_t)(kc * 16 + mb) * 8192 +
               (size_t)((((wm4 * 4 + mt) * 4 + ks8) * 32 + lane2) * 4 + r);
    };

#pragma unroll
    for (int dn = 0; dn < 8; dn++) {
        int cbase = h * 64 + dn * 8 + (lq << 1);
        AOP[paddr(grow, cbase)]         = f2tff(o[dn][0] * i0);
        AOP[paddr(grow, cbase + 1)]     = f2tff(o[dn][1] * i0);
        AOP[paddr(grow + 8, cbase)]     = f2tff(o[dn][2] * i1);
        AOP[paddr(grow + 8, cbase + 1)] = f2tff(o[dn][3] * i1);
    }
}

// ---------------------------------------------------------------------------
extern "C" void kernel_launch(void* const* d_in, const int* in_sizes, int n_in,
                              void* d_out, int out_size) {
    const float* x = (const float*)d_in[0];
    const float* w_qkv = (const float*)d_in[1];
    const float* w_out = (const float*)d_in[2];
    const float* freqs = (const float*)d_in[3];
    float* out = (float*)d_out;

    float *q, *k, *v, *xp, *wp, *wop, *aop, *cb, *sb;
    cudaGetSymbolAddress((void**)&q, g_q);
    cudaGetSymbolAddress((void**)&k, g_k);
    cudaGetSymbolAddress((void**)&v, g_v);
    cudaGetSymbolAddress((void**)&xp, g_xp);
    cudaGetSymbolAddress((void**)&wp, g_wp);
    cudaGetSymbolAddress((void**)&wop, g_wop);
    cudaGetSymbolAddress((void**)&aop, g_aop);
    cudaGetSymbolAddress((void**)&cb, g_cos);
    cudaGetSymbolAddress((void**)&sb, g_sin);

    cudaFuncSetAttribute(attn_kernel,
                         cudaFuncAttributeMaxDynamicSharedMemorySize,
                         ATTN_SMEM_BYTES);
    cudaFuncSetAttribute(gemm_qkv,
                         cudaFuncAttributeMaxDynamicSharedMemorySize,
                         GEMM_SMEM);
    cudaFuncSetAttribute(gemm_out,
                         cudaFuncAttributeMaxDynamicSharedMemorySize,
                         GEMM_SMEM);

    // 0) Pack operands (fragment order) + trig tables
    pack_a<<<4096, 256>>>(x, xp);                       // 1M quads
    pack_b<<<(32 * 24 * 2048) / 256, 256>>>(w_qkv, wp, 3072);
    pack_b<<<(32 * 8 * 2048) / 256, 256>>>(w_out, wop, 1024);
    trig_kernel<<<(Ss * DH) / 256, 256>>>(freqs, cb, sb);

    // 1) QKV projection + fused RoPE -> q/k/v in [b,h,s,d] (tf32)
    gemm_qkv<<<dim3(24, 16), 256, GEMM_SMEM>>>(xp, wp, q, k, v, cb, sb);
    // 2) Causal flash attention (writes fragment-packed aop)
    attn_kernel<<<dim3(Ss / 128, Hh, Bb), 256, ATTN_SMEM_BYTES>>>(q, k, v, aop);
    // 3) Output projection
    gemm_out<<<dim3(8, 16), 256, GEMM_SMEM>>>(aop, wop, out);
}

// round 15
// speedup vs baseline: 1.0726x; 1.0375x over previous
#include <cuda_runtime.h>
#include <cstdint>

// Problem constants
static constexpr int Bb = 2, Ss = 2048, Hh = 16, DH = 64, Dd = 1024;
static constexpr int KC32 = 32;                 // 1024 / 32 k-steps

// Scratch (static device globals — no allocations allowed)
__device__ float g_q[Bb * Hh * Ss * DH];        // rope'd, scaled(*log2e), tf32
__device__ float g_k[Bb * Hh * Ss * DH];        // fragment-PAIR packed per 64-row tile
__device__ float g_v[Bb * Hh * Ss * DH];        // fragment-PAIR packed (perm baked)
__device__ float g_xp[32 * 4096 * 32];          // frag-packed A gemm1
__device__ float g_wp[32 * 24 * 4096];          // frag-packed B w_qkv
__device__ float g_wop[32 * 8 * 4096];          // frag-packed B w_out
__device__ float g_aop[32 * 4096 * 32];         // frag-packed A gemm2
__device__ float g_cos[Ss * DH];                // cos(freqs)
__device__ float g_sin[Ss * DH];                // sin(freqs)

__device__ __forceinline__ uint32_t f2tf(float f) {
    uint32_t u;
    asm("cvt.rna.tf32.f32 %0, %1;" : "=r"(u) : "f"(f));
    return u;
}
__device__ __forceinline__ float f2tff(float f) { return __uint_as_float(f2tf(f)); }

__device__ __forceinline__ float ex2(float x) {
    float y;
    asm("ex2.approx.f32 %0, %1;" : "=f"(y) : "f"(x));
    return y;
}

__device__ __forceinline__ void cp16(void* smem_ptr, const void* gptr) {
    uint32_t sa = (uint32_t)__cvta_generic_to_shared(smem_ptr);
    asm volatile("cp.async.ca.shared.global [%0], [%1], 16;"
                 :: "r"(sa), "l"(gptr));
}

__device__ __forceinline__ void mma8(float (&c)[4], const uint32_t (&a)[4],
                                     uint32_t b0, uint32_t b1) {
    asm volatile(
        "mma.sync.aligned.m16n8k8.row.col.f32.tf32.tf32.f32 "
        "{%0,%1,%2,%3}, {%4,%5,%6,%7}, {%8,%9}, {%0,%1,%2,%3};"
        : "+f"(c[0]), "+f"(c[1]), "+f"(c[2]), "+f"(c[3])
        : "r"(a[0]), "r"(a[1]), "r"(a[2]), "r"(a[3]), "r"(b0), "r"(b1));
}

// ---- mbarrier + 1D bulk-copy helpers ----
__device__ __forceinline__ uint32_t s2u(const void* p) {
    return (uint32_t)__cvta_generic_to_shared(p);
}
__device__ __forceinline__ void mbar_init(uint32_t addr, uint32_t cnt) {
    asm volatile("mbarrier.init.shared.b64 [%0], %1;" :: "r"(addr), "r"(cnt));
}
__device__ __forceinline__ void mbar_expect_tx(uint32_t addr, uint32_t bytes) {
    asm volatile("mbarrier.arrive.expect_tx.shared.b64 _, [%0], %1;"
                 :: "r"(addr), "r"(bytes));
}
__device__ __forceinline__ void mbar_wait(uint32_t addr, uint32_t parity) {
    asm volatile(
        "{\n\t.reg .pred P;\n"
        "W%=:\n\t"
        "mbarrier.try_wait.parity.shared.b64 P, [%0], %1;\n\t"
        "@!P bra W%=;\n\t}"
        :: "r"(addr), "r"(parity) : "memory");
}
__device__ __forceinline__ void bulk_g2s(uint32_t dst, const void* src,
                                         uint32_t bytes, uint32_t mbar) {
    asm volatile(
        "cp.async.bulk.shared::cta.global.mbarrier::complete_tx::bytes "
        "[%0], [%1], %2, [%3];"
        :: "r"(dst), "l"(src), "r"(bytes), "r"(mbar) : "memory");
}

// ---------------------------------------------------------------------------
// Fragment-packed A/B pack kernels (R14 proven, unchanged).
// ---------------------------------------------------------------------------
__global__ __launch_bounds__(256) void pack_a(
    const float* __restrict__ X, float* __restrict__ Xp) {
    int idx = blockIdx.x * 256 + threadIdx.x;   // 1M quads
    int lane = idx & 31;
    int ks8 = (idx >> 5) & 3;
    int mt = (idx >> 7) & 3;
    int wm4 = (idx >> 9) & 3;
    int mb = (idx >> 11) & 15;
    int kc = idx >> 15;
    int row = mb * 256 + wm4 * 64 + mt * 16 + (lane >> 2);
    int c = kc * 32 + ks8 * 8 + (lane & 3);
    const float* xr = X + (size_t)row * 1024 + c;
    float4 q = make_float4(f2tff(xr[0]), f2tff(xr[8192]),      // +8 rows
                           f2tff(xr[4]), f2tff(xr[8196]));
    *(float4*)&Xp[(size_t)idx * 4] = q;
}

__global__ __launch_bounds__(256) void pack_b(
    const float* __restrict__ W, float* __restrict__ Wp, int N) {
    int idx = blockIdx.x * 256 + threadIdx.x;
    int NB = N >> 7;
    int per_kc = NB << 11;
    int kc = idx / per_kc;
    int rem = idx - kc * per_kc;
    int nb = rem >> 11;
    int w = rem & 2047;
    int lane = w & 31;
    int ks8 = (w >> 5) & 3;
    int nt = (w >> 7) & 7;
    int wn2 = (w >> 10) & 1;
    int col = nb * 128 + wn2 * 64 + nt * 8 + (lane >> 2);
    int k0 = kc * 32 + ks8 * 8 + (lane & 3);
    const float* wr = W + (size_t)k0 * N + col;
    *(float2*)&Wp[(size_t)idx * 2] =
        make_float2(f2tff(wr[0]), f2tff(wr[4 * N]));
}

// cos/sin tables for the fused-rope GEMM epilogue (precise sincosf, once).
__global__ __launch_bounds__(256) void trig_kernel(
    const float* __restrict__ freqs, float* __restrict__ cb,
    float* __restrict__ sb) {
    int i = blockIdx.x * 256 + threadIdx.x;     // 2048*64
    float s, c;
    sincosf(freqs[i], &s, &c);
    cb[i] = c;
    sb[i] = s;
}

// ---------------------------------------------------------------------------
// GEMM mainloop (R14 proven): 256x128 tile, BK=32, fragment-packed smem.
// ---------------------------------------------------------------------------
static constexpr int AST_W = 256 * 32;          // 8192 words
static constexpr int BST_W = 32 * 128;          // 4096 words
static constexpr int STG_W = AST_W + BST_W;     // 12288 words = 49152 B
static constexpr int GEMM_SMEM = 3 * STG_W * 4; // 147456 B

#define GEMM_MAINLOOP(ApPtr, BpPtr, NBv)                                      \
    extern __shared__ uint32_t gsm[];                                         \
    __shared__ uint64_t gmb[3];                                               \
    const int tid = threadIdx.x, lane = tid & 31, warp = tid >> 5;            \
    const int wm = (warp >> 1) * 64, wn = (warp & 1) * 64;                    \
    const int warpm = warp >> 1, wn2 = warp & 1;                              \
    const int lr = lane >> 2, lq = lane & 3;                                  \
    const int bm = blockIdx.y * 256, nb = blockIdx.x;                         \
    const uint32_t mb0 = s2u(gmb);                                            \
    const uint32_t smem_base = s2u(gsm);                                      \
    if (tid == 0) {                                                           \
        mbar_init(mb0, 1);                                                    \
        mbar_init(mb0 + 8, 1);                                                \
        mbar_init(mb0 + 16, 1);                                               \
        asm volatile("fence.proxy.async.shared::cta;" ::: "memory");          \
    }                                                                         \
    __syncthreads();                                                          \
    auto issue = [&](int i) {                                                 \
        if (tid == 0) {                                                       \
            int st = i % 3;                                                   \
            uint32_t m = mb0 + st * 8;                                        \
            uint32_t dst = smem_base + st * (STG_W * 4);                      \
            mbar_expect_tx(m, STG_W * 4);                                     \
            bulk_g2s(dst, (ApPtr) + (size_t)(i * 16 + blockIdx.y) * 8192,     \
                     AST_W * 4, m);                                           \
            bulk_g2s(dst + AST_W * 4, (BpPtr) + (size_t)(i * (NBv) + nb) *    \
                     4096, BST_W * 4, m);                                     \
        }                                                                     \
    };                                                                        \
    float acc[4][8][4];                                                       \
    _Pragma("unroll") for (int mt = 0; mt < 4; mt++)                          \
        _Pragma("unroll") for (int nt = 0; nt < 8; nt++)                      \
            _Pragma("unroll") for (int i = 0; i < 4; i++)                     \
                acc[mt][nt][i] = 0.f;                                         \
    issue(0);                                                                 \
    issue(1);                                                                 \
    issue(2);                                                                 \
    for (int i = 0; i < KC32; i++) {                                          \
        const int st = i % 3;                                                 \
        mbar_wait(mb0 + st * 8, (i / 3) & 1);                                 \
        const uint32_t* As = gsm + st * STG_W;                                \
        const uint32_t* Bs = As + AST_W;                                      \
        _Pragma("unroll") for (int ks8 = 0; ks8 < 4; ks8++) {                 \
            uint32_t a[4][4], b[8][2];                                        \
            _Pragma("unroll") for (int mt = 0; mt < 4; mt++) {                \
                uint4 av = *(const uint4*)&As[                                \
                    ((warpm * 16 + mt * 4 + ks8) * 32 + lane) * 4];           \
                a[mt][0] = av.x; a[mt][1] = av.y;                             \
                a[mt][2] = av.z; a[mt][3] = av.w;                             \
            }                                                                 \
            _Pragma("unroll") for (int nt = 0; nt < 8; nt++) {                \
                uint2 bv = *(const uint2*)&Bs[                                \
                    ((wn2 * 32 + nt * 4 + ks8) * 32 + lane) * 2];             \
                b[nt][0] = bv.x; b[nt][1] = bv.y;                             \
            }                                                                 \
            _Pragma("unroll") for (int mt = 0; mt < 4; mt++)                  \
                _Pragma("unroll") for (int nt = 0; nt < 8; nt++)              \
                    mma8(acc[mt][nt], a[mt], b[nt][0], b[nt][1]);             \
        }                                                                     \
        __syncthreads();                                                      \
        if (i + 3 < KC32) issue(i + 3);                                       \
    }

// ---------------------------------------------------------------------------
// GEMM 1: QKV projection with fused RoPE. Q written row-major [b,h,s,d];
// K/V written in attention's b-fragment PAIR layout per 64-row tile:
//   K word: 2*((k8*8 + (rr>>3))*32 + 4*(rr&7) + (d&3)) + ((d>>2)&1)
//   V word: 2*(((rr>>3)*8 + nt)*32 + 4*(d&7) + ((rr&7)>>1)) + (rr&1)
// ---------------------------------------------------------------------------
__global__ __launch_bounds__(256) void gemm_qkv(
    const float* __restrict__ Ap, const float* __restrict__ Bp,
    float* __restrict__ Qo, float* __restrict__ Ko, float* __restrict__ Vo,
    const float* __restrict__ cb, const float* __restrict__ sb) {
    GEMM_MAINLOOP(Ap, Bp, 24)

    const int col0 = nb * 128 + wn;             // 64-col slice start
    const int type = col0 >> 10;                // 0=q, 1=k, 2=v
    const int h = (col0 >> 6) & 15;
    const float qsc = 0.125f * 1.4426950408889634f;

    if (type == 0) {
#pragma unroll
        for (int mt = 0; mt < 4; mt++) {
#pragma unroll
            for (int e2 = 0; e2 < 2; e2++) {
                int r = bm + wm + mt * 16 + lr + 8 * e2;
                int s = r & 2047, bbx = r >> 11;
                float* dst = Qo + ((size_t)(bbx * Hh + h) * Ss + s) * 64;
                const float* cr = cb + s * 64;
                const float* sr = sb + s * 64;
#pragma unroll
                for (int nt = 0; nt < 4; nt++) {
                    int dlo = nt * 8 + (lq << 1);
                    float2 clo = *(const float2*)&cr[dlo];
                    float2 slo = *(const float2*)&sr[dlo];
                    float2 chi = *(const float2*)&cr[dlo + 32];
                    float2 shi = *(const float2*)&sr[dlo + 32];
                    float al0 = acc[mt][nt][2 * e2], al1 = acc[mt][nt][2 * e2 + 1];
                    float ah0 = acc[mt][nt + 4][2 * e2], ah1 = acc[mt][nt + 4][2 * e2 + 1];
                    float ol0 = (al0 * clo.x - ah0 * slo.x) * qsc;
                    float ol1 = (al1 * clo.y - ah1 * slo.y) * qsc;
                    float oh0 = (ah0 * chi.x + al0 * shi.x) * qsc;
                    float oh1 = (ah1 * chi.y + al1 * shi.y) * qsc;
                    *(float2*)&dst[dlo] = make_float2(f2tff(ol0), f2tff(ol1));
                    *(float2*)&dst[dlo + 32] = make_float2(f2tff(oh0), f2tff(oh1));
                }
            }
        }
    } else if (type == 1) {
#pragma unroll
        for (int mt = 0; mt < 4; mt++) {
#pragma unroll
            for (int e2 = 0; e2 < 2; e2++) {
                int r = bm + wm + mt * 16 + lr + 8 * e2;
                int s = r & 2047, bbx = r >> 11;
                float* dst = Ko + ((size_t)(bbx * Hh + h) * Ss + (s & ~63)) * 64;
                int rr = s & 63;
                int ntv = rr >> 3, lrv = rr & 7;
                const float* cr = cb + s * 64;
                const float* sr = sb + s * 64;
#pragma unroll
                for (int nt = 0; nt < 4; nt++) {
                    int dlo = nt * 8 + (lq << 1);
                    float2 clo = *(const float2*)&cr[dlo];
                    float2 slo = *(const float2*)&sr[dlo];
                    float2 chi = *(const float2*)&cr[dlo + 32];
                    float2 shi = *(const float2*)&sr[dlo + 32];
                    float al0 = acc[mt][nt][2 * e2], al1 = acc[mt][nt][2 * e2 + 1];
                    float ah0 = acc[mt][nt + 4][2 * e2], ah1 = acc[mt][nt + 4][2 * e2 + 1];
                    float v4[4] = {al0 * clo.x - ah0 * slo.x,
                                   al1 * clo.y - ah1 * slo.y,
                                   ah0 * chi.x + al0 * shi.x,
                                   ah1 * chi.y + al1 * shi.y};
                    int d4[4] = {dlo, dlo + 1, dlo + 32, dlo + 33};
#pragma unroll
                    for (int j = 0; j < 4; j++) {
                        int d = d4[j];
                        int k8 = d >> 3, e = (d >> 2) & 1, lqv = d & 3;
                        dst[2 * ((k8 * 8 + ntv) * 32 + 4 * lrv + lqv) + e] =
                            f2tff(v4[j]);
                    }
                }
            }
        }
    } else {
#pragma unroll
        for (int mt = 0; mt < 4; mt++) {
#pragma unroll
            for (int e2 = 0; e2 < 2; e2++) {
                int r = bm + wm + mt * 16 + lr + 8 * e2;
                int s = r & 2047, bbx = r >> 11;
                float* dst = Vo + ((size_t)(bbx * Hh + h) * Ss + (s & ~63)) * 64;
                int rr = s & 63;
                int k8v = rr >> 3, g = rr & 7;
                int lqv = g >> 1, ev = g & 1;       // permutation baked in
#pragma unroll
                for (int nt = 0; nt < 8; nt++) {
                    int d0 = nt * 8 + (lq << 1);
                    float v0 = acc[mt][nt][2 * e2], v1 = acc[mt][nt][2 * e2 + 1];
                    int lrv0 = d0 & 7, lrv1 = (d0 + 1) & 7;
                    dst[2 * ((k8v * 8 + nt) * 32 + 4 * lrv0 + lqv) + ev] = f2tff(v0);
                    dst[2 * ((k8v * 8 + nt) * 32 + 4 * lrv1 + lqv) + ev] = f2tff(v1);
                }
            }
        }
    }
}

// ---------------------------------------------------------------------------
// GEMM 2: output projection, plain row-major epilogue.
// ---------------------------------------------------------------------------
__global__ __launch_bounds__(256) void gemm_out(
    const float* __restrict__ Ap, const float* __restrict__ Bp,
    float* __restrict__ C) {
    GEMM_MAINLOOP(Ap, Bp, 8)

#pragma unroll
    for (int mt = 0; mt < 4; mt++)
#pragma unroll
        for (int nt = 0; nt < 8; nt++) {
            int row = bm + wm + mt * 16 + lr;
            int col = (nb << 7) + wn + nt * 8 + (lq << 1);
            *(float2*)&C[(size_t)row * 1024 + col] =
                make_float2(acc[mt][nt][0], acc[mt][nt][1]);
            *(float2*)&C[(size_t)(row + 8) * 1024 + col] =
                make_float2(acc[mt][nt][2], acc[mt][nt][3]);
        }
}

// ---------------------------------------------------------------------------
// Causal flash attention: K/V b-fragments loaded with single LDS.64 from
// pair-packed tiles (no padding, linear cp.async loader). 2 CTAs/SM.
// Epilogue writes FRAGMENT-PACKED aop for gemm2 (R14 proven).
// ---------------------------------------------------------------------------
static constexpr int ATTN_STAGE_W = 8192;            // K 4096 + V 4096 words
static constexpr int ATTN_SMEM_BYTES = 2 * ATTN_STAGE_W * 4;   // 65536 B

__global__ __launch_bounds__(256, 2) void attn_kernel(
    const float* __restrict__ Q, const float* __restrict__ K,
    const float* __restrict__ V, float* __restrict__ AOP) {
    extern __shared__ uint32_t dynsmem[];

    const int qt = gridDim.x - 1 - blockIdx.x;
    const int h = blockIdx.y, b = blockIdx.z;
    const int tid = threadIdx.x, lane = tid & 31, warp = tid >> 5;
    const int lr = lane >> 2, lq = lane & 3;
    const int q0 = qt * 128;

    const size_t bh = (size_t)(b * Hh + h) * Ss;
    const float* Qg = Q + (bh + q0) * 64;
    const float* Kg = K + bh * 64;
    const float* Vg = V + bh * 64;

    uint32_t qf[8][4];
    {
        int r0 = warp * 16 + lr;
#pragma unroll
        for (int k8 = 0; k8 < 8; k8++) {
            int c = k8 * 8 + lq;
            qf[k8][0] = __float_as_uint(Qg[r0 * 64 + c]);
            qf[k8][1] = __float_as_uint(Qg[(r0 + 8) * 64 + c]);
            qf[k8][2] = __float_as_uint(Qg[r0 * 64 + c + 4]);
            qf[k8][3] = __float_as_uint(Qg[(r0 + 8) * 64 + c + 4]);
        }
    }

    float o[8][4];
#pragma unroll
    for (int dn = 0; dn < 8; dn++)
#pragma unroll
        for (int i = 0; i < 4; i++) o[dn][i] = 0.f;
    float m0 = -1e30f, m1 = -1e30f, l0 = 0.f, l1 = 0.f;

    auto issue_tile = [&](int jt, int buf) {
        const float* kb = Kg + (size_t)(jt * 64) * 64;
        const float* vb = Vg + (size_t)(jt * 64) * 64;
        uint32_t* Kd = dynsmem + buf * ATTN_STAGE_W;
#pragma unroll
        for (int u = 0; u < 4; u++) {
            int w = (u * 256 + tid) * 4;
            cp16(&Kd[w], kb + w);
            cp16(&Kd[4096 + w], vb + w);
        }
        asm volatile("cp.async.commit_group;");
    };

    const int jmax = 2 * qt + 1;
    issue_tile(0, 0);

    for (int jt = 0; jt <= jmax; jt++) {
        const int cur = jt & 1;
        if (jt < jmax) {
            issue_tile(jt + 1, cur ^ 1);
            asm volatile("cp.async.wait_group 1;");
        } else {
            asm volatile("cp.async.wait_group 0;");
        }
        __syncthreads();

        const uint32_t* Ksb = dynsmem + cur * ATTN_STAGE_W;
        const uint32_t* Vsb = Ksb + 4096;

        float sc[8][4];
#pragma unroll
        for (int nt = 0; nt < 8; nt++)
#pragma unroll
            for (int i = 0; i < 4; i++) sc[nt][i] = 0.f;
#pragma unroll
        for (int k8 = 0; k8 < 8; k8++)
#pragma unroll
            for (int nt = 0; nt < 8; nt++) {
                uint2 kv = *(const uint2*)&Ksb[((k8 * 8 + nt) * 32 + lane) * 2];
                mma8(sc[nt], qf[k8], kv.x, kv.y);
            }

        if (jt >= 2 * qt) {
            int r1 = q0 + warp * 16 + lr;
#pragma unroll
            for (int nt = 0; nt < 8; nt++) {
                int key = jt * 64 + nt * 8 + (lq << 1);
                if (key > r1) sc[nt][0] = -1e30f;
                if (key + 1 > r1) sc[nt][1] = -1e30f;
                if (key > r1 + 8) sc[nt][2] = -1e30f;
                if (key + 1 > r1 + 8) sc[nt][3] = -1e30f;
            }
        }

        float mx0 = -1e30f, mx1 = -1e30f;
#pragma unroll
        for (int nt = 0; nt < 8; nt++) {
            mx0 = fmaxf(mx0, fmaxf(sc[nt][0], sc[nt][1]));
            mx1 = fmaxf(mx1, fmaxf(sc[nt][2], sc[nt][3]));
        }
        mx0 = fmaxf(mx0, __shfl_xor_sync(0xffffffffu, mx0, 1));
        mx0 = fmaxf(mx0, __shfl_xor_sync(0xffffffffu, mx0, 2));
        mx1 = fmaxf(mx1, __shfl_xor_sync(0xffffffffu, mx1, 1));
        mx1 = fmaxf(mx1, __shfl_xor_sync(0xffffffffu, mx1, 2));
        float mn0 = fmaxf(m0, mx0), mn1 = fmaxf(m1, mx1);
        float fac0 = ex2(m0 - mn0), fac1 = ex2(m1 - mn1);

        float s0 = 0.f, s1 = 0.f;
#pragma unroll
        for (int nt = 0; nt < 8; nt++) {
            float p0 = ex2(sc[nt][0] - mn0);
            float p1 = ex2(sc[nt][1] - mn0);
            float p2 = ex2(sc[nt][2] - mn1);
            float p3 = ex2(sc[nt][3] - mn1);
            s0 += p0 + p1;
            s1 += p2 + p3;
            sc[nt][0] = p0;     // raw fp32 -> mma (HW tf32 truncation)
            sc[nt][1] = p1;
            sc[nt][2] = p2;
            sc[nt][3] = p3;
        }
        s0 += __shfl_xor_sync(0xffffffffu, s0, 1);
        s0 += __shfl_xor_sync(0xffffffffu, s0, 2);
        s1 += __shfl_xor_sync(0xffffffffu, s1, 1);
        s1 += __shfl_xor_sync(0xffffffffu, s1, 2);
        l0 = l0 * fac0 + s0;
        l1 = l1 * fac1 + s1;
        m0 = mn0;
        m1 = mn1;
#pragma unroll
        for (int dn = 0; dn < 8; dn++) {
            o[dn][0] *= fac0; o[dn][1] *= fac0;
            o[dn][2] *= fac1; o[dn][3] *= fac1;
        }

#pragma unroll
        for (int k8 = 0; k8 < 8; k8++) {
            uint32_t af[4] = {__float_as_uint(sc[k8][0]), __float_as_uint(sc[k8][2]),
                              __float_as_uint(sc[k8][1]), __float_as_uint(sc[k8][3])};
#pragma unroll
            for (int dn = 0; dn < 8; dn++) {
                uint2 vv = *(const uint2*)&Vsb[((k8 * 8 + dn) * 32 + lane) * 2];
                mma8(o[dn], af, vv.x, vv.y);
            }
        }
        __syncthreads();
    }

    // ---- epilogue: normalize + tf32, write FRAGMENT-PACKED aop ----
    float i0 = 1.0f / l0, i1 = 1.0f / l1;
    int grow = b * Ss + q0 + warp * 16 + lr;

    auto paddr = [](int row, int c) -> size_t {
        int kc = c >> 5;
        int mb = row >> 8;
        int wm4 = (row >> 6) & 3;
        int mt = (row >> 4) & 3;
        int lane2 = ((row & 7) << 2) | (c & 3);
        int r = (((c >> 2) & 1) << 1) | ((row >> 3) & 1);
        int ks8 = (c >> 3) & 3;
        return (size_t)(kc * 16 + mb) * 8192 +
               (size_t)((((wm4 * 4 + mt) * 4 + ks8) * 32 + lane2) * 4 + r);
    };

#pragma unroll
    for (int dn = 0; dn < 8; dn++) {
        int cbase = h * 64 + dn * 8 + (lq << 1);
        AOP[paddr(grow, cbase)]         = f2tff(o[dn][0] * i0);
        AOP[paddr(grow, cbase + 1)]     = f2tff(o[dn][1] * i0);
        AOP[paddr(grow + 8, cbase)]     = f2tff(o[dn][2] * i1);
        AOP[paddr(grow + 8, cbase + 1)] = f2tff(o[dn][3] * i1);
    }
}

// ---------------------------------------------------------------------------
extern "C" void kernel_launch(void* const* d_in, const int* in_sizes, int n_in,
                              void* d_out, int out_size) {
    const float* x = (const float*)d_in[0];
    const float* w_qkv = (const float*)d_in[1];
    const float* w_out = (const float*)d_in[2];
    const float* freqs = (const float*)d_in[3];
    float* out = (float*)d_out;

    float *q, *k, *v, *xp, *wp, *wop, *aop, *cb, *sb;
    cudaGetSymbolAddress((void**)&q, g_q);
    cudaGetSymbolAddress((void**)&k, g_k);
    cudaGetSymbolAddress((void**)&v, g_v);
    cudaGetSymbolAddress((void**)&xp, g_xp);
    cudaGetSymbolAddress((void**)&wp, g_wp);
    cudaGetSymbolAddress((void**)&wop, g_wop);
    cudaGetSymbolAddress((void**)&aop, g_aop);
    cudaGetSymbolAddress((void**)&cb, g_cos);
    cudaGetSymbolAddress((void**)&sb, g_sin);

    cudaFuncSetAttribute(attn_kernel,
                         cudaFuncAttributeMaxDynamicSharedMemorySize,
                         ATTN_SMEM_BYTES);
    cudaFuncSetAttribute(gemm_qkv,
                         cudaFuncAttributeMaxDynamicSharedMemorySize,
                         GEMM_SMEM);
    cudaFuncSetAttribute(gemm_out,
                         cudaFuncAttributeMaxDynamicSharedMemorySize,
                         GEMM_SMEM);

    // 0) Pack operands (fragment order) + trig tables
    pack_a<<<4096, 256>>>(x, xp);                       // 1M quads
    pack_b<<<(32 * 24 * 2048) / 256, 256>>>(w_qkv, wp, 3072);
    pack_b<<<(32 * 8 * 2048) / 256, 256>>>(w_out, wop, 1024);
    trig_kernel<<<(Ss * DH) / 256, 256>>>(freqs, cb, sb);

    // 1) QKV projection + fused RoPE -> q row-major, k/v pair-packed
    gemm_qkv<<<dim3(24, 16), 256, GEMM_SMEM>>>(xp, wp, q, k, v, cb, sb);
    // 2) Causal flash attention (LDS.64 b-frags; writes frag-packed aop)
    attn_kernel<<<dim3(Ss / 128, Hh, Bb), 256, ATTN_SMEM_BYTES>>>(q, k, v, aop);
    // 3) Output projection
    gemm_out<<<dim3(8, 16), 256, GEMM_SMEM>>>(aop, wop, out);
}

// round 16
// speedup vs baseline: 1.1841x; 1.1039x over previous
#include <cuda_runtime.h>
#include <cstdint>

// Problem constants
static constexpr int Bb = 2, Ss = 2048, Hh = 16, DH = 64, Dd = 1024;
static constexpr int KC32 = 32;                 // 1024 / 32 k-steps

// Scratch (static device globals — no allocations allowed)
__device__ float g_q[Bb * Hh * Ss * DH];        // rope'd, scaled(*log2e), tf32
__device__ float g_k[Bb * Hh * Ss * DH];        // fragment-PAIR packed per 64-row tile
__device__ float g_v[Bb * Hh * Ss * DH];        // fragment-PAIR packed (perm baked)
__device__ float g_xp[32 * 4096 * 32];          // frag-packed A gemm1
__device__ float g_wp[32 * 24 * 4096];          // frag-packed B w_qkv
__device__ float g_wop[32 * 8 * 4096];          // frag-packed B w_out
__device__ float g_aop[32 * 4096 * 32];         // frag-packed A gemm2
__device__ float g_cos[Ss * DH];                // cos(freqs)
__device__ float g_sin[Ss * DH];                // sin(freqs)

__device__ __forceinline__ uint32_t f2tf(float f) {
    uint32_t u;
    asm("cvt.rna.tf32.f32 %0, %1;" : "=r"(u) : "f"(f));
    return u;
}
__device__ __forceinline__ float f2tff(float f) { return __uint_as_float(f2tf(f)); }

__device__ __forceinline__ float ex2(float x) {
    float y;
    asm("ex2.approx.f32 %0, %1;" : "=f"(y) : "f"(x));
    return y;
}

__device__ __forceinline__ void cp16(void* smem_ptr, const void* gptr) {
    uint32_t sa = (uint32_t)__cvta_generic_to_shared(smem_ptr);
    asm volatile("cp.async.ca.shared.global [%0], [%1], 16;"
                 :: "r"(sa), "l"(gptr));
}

__device__ __forceinline__ void mma8(float (&c)[4], const uint32_t (&a)[4],
                                     uint32_t b0, uint32_t b1) {
    asm volatile(
        "mma.sync.aligned.m16n8k8.row.col.f32.tf32.tf32.f32 "
        "{%0,%1,%2,%3}, {%4,%5,%6,%7}, {%8,%9}, {%0,%1,%2,%3};"
        : "+f"(c[0]), "+f"(c[1]), "+f"(c[2]), "+f"(c[3])
        : "r"(a[0]), "r"(a[1]), "r"(a[2]), "r"(a[3]), "r"(b0), "r"(b1));
}

// ---- mbarrier + 1D bulk-copy helpers ----
__device__ __forceinline__ uint32_t s2u(const void* p) {
    return (uint32_t)__cvta_generic_to_shared(p);
}
__device__ __forceinline__ void mbar_init(uint32_t addr, uint32_t cnt) {
    asm volatile("mbarrier.init.shared.b64 [%0], %1;" :: "r"(addr), "r"(cnt));
}
__device__ __forceinline__ void mbar_expect_tx(uint32_t addr, uint32_t bytes) {
    asm volatile("mbarrier.arrive.expect_tx.shared.b64 _, [%0], %1;"
                 :: "r"(addr), "r"(bytes));
}
__device__ __forceinline__ void mbar_wait(uint32_t addr, uint32_t parity) {
    asm volatile(
        "{\n\t.reg .pred P;\n"
        "W%=:\n\t"
        "mbarrier.try_wait.parity.shared.b64 P, [%0], %1;\n\t"
        "@!P bra W%=;\n\t}"
        :: "r"(addr), "r"(parity) : "memory");
}
__device__ __forceinline__ void bulk_g2s(uint32_t dst, const void* src,
                                         uint32_t bytes, uint32_t mbar) {
    asm volatile(
        "cp.async.bulk.shared::cta.global.mbarrier::complete_tx::bytes "
        "[%0], [%1], %2, [%3];"
        :: "r"(dst), "l"(src), "r"(bytes), "r"(mbar) : "memory");
}

// ---------------------------------------------------------------------------
// Fragment-packed A/B pack kernels (R14 proven, unchanged).
// ---------------------------------------------------------------------------
__global__ __launch_bounds__(256) void pack_a(
    const float* __restrict__ X, float* __restrict__ Xp) {
    int idx = blockIdx.x * 256 + threadIdx.x;   // 1M quads
    int lane = idx & 31;
    int ks8 = (idx >> 5) & 3;
    int mt = (idx >> 7) & 3;
    int wm4 = (idx >> 9) & 3;
    int mb = (idx >> 11) & 15;
    int kc = idx >> 15;
    int row = mb * 256 + wm4 * 64 + mt * 16 + (lane >> 2);
    int c = kc * 32 + ks8 * 8 + (lane & 3);
    const float* xr = X + (size_t)row * 1024 + c;
    float4 q = make_float4(f2tff(xr[0]), f2tff(xr[8192]),      // +8 rows
                           f2tff(xr[4]), f2tff(xr[8196]));
    *(float4*)&Xp[(size_t)idx * 4] = q;
}

__global__ __launch_bounds__(256) void pack_b(
    const float* __restrict__ W, float* __restrict__ Wp, int N) {
    int idx = blockIdx.x * 256 + threadIdx.x;
    int NB = N >> 7;
    int per_kc = NB << 11;
    int kc = idx / per_kc;
    int rem = idx - kc * per_kc;
    int nb = rem >> 11;
    int w = rem & 2047;
    int lane = w & 31;
    int ks8 = (w >> 5) & 3;
    int nt = (w >> 7) & 7;
    int wn2 = (w >> 10) & 1;
    int col = nb * 128 + wn2 * 64 + nt * 8 + (lane >> 2);
    int k0 = kc * 32 + ks8 * 8 + (lane & 3);
    const float* wr = W + (size_t)k0 * N + col;
    *(float2*)&Wp[(size_t)idx * 2] =
        make_float2(f2tff(wr[0]), f2tff(wr[4 * N]));
}

// cos/sin tables for the fused-rope GEMM epilogue (precise sincosf, once).
__global__ __launch_bounds__(256) void trig_kernel(
    const float* __restrict__ freqs, float* __restrict__ cb,
    float* __restrict__ sb) {
    int i = blockIdx.x * 256 + threadIdx.x;     // 2048*64
    float s, c;
    sincosf(freqs[i], &s, &c);
    cb[i] = c;
    sb[i] = s;
}

// ---------------------------------------------------------------------------
// GEMM mainloop: 256x128 tile, BK=32, fragment-packed smem, now 2-STAGE
// pipeline (98.3KB smem -> 2 CTAs/SM, kills the 3-wave quantization tail).
// ---------------------------------------------------------------------------
static constexpr int AST_W = 256 * 32;          // 8192 words
static constexpr int BST_W = 32 * 128;          // 4096 words
static constexpr int STG_W = AST_W + BST_W;     // 12288 words = 49152 B
static constexpr int GEMM_SMEM = 2 * STG_W * 4; // 98304 B

#define GEMM_MAINLOOP(ApPtr, BpPtr, NBv)                                      \
    extern __shared__ uint32_t gsm[];                                         \
    __shared__ uint64_t gmb[2];                                               \
    const int tid = threadIdx.x, lane = tid & 31, warp = tid >> 5;            \
    const int wm = (warp >> 1) * 64, wn = (warp & 1) * 64;                    \
    const int warpm = warp >> 1, wn2 = warp & 1;                              \
    const int lr = lane >> 2, lq = lane & 3;                                  \
    const int bm = blockIdx.y * 256, nb = blockIdx.x;                         \
    const uint32_t mb0 = s2u(gmb);                                            \
    const uint32_t smem_base = s2u(gsm);                                      \
    if (tid == 0) {                                                           \
        mbar_init(mb0, 1);                                                    \
        mbar_init(mb0 + 8, 1);                                                \
        asm volatile("fence.proxy.async.shared::cta;" ::: "memory");          \
    }                                                                         \
    __syncthreads();                                                          \
    auto issue = [&](int i) {                                                 \
        if (tid == 0) {                                                       \
            int st = i & 1;                                                   \
            uint32_t m = mb0 + st * 8;                                        \
            uint32_t dst = smem_base + st * (STG_W * 4);                      \
            mbar_expect_tx(m, STG_W * 4);                                     \
            bulk_g2s(dst, (ApPtr) + (size_t)(i * 16 + blockIdx.y) * 8192,     \
                     AST_W * 4, m);                                           \
            bulk_g2s(dst + AST_W * 4, (BpPtr) + (size_t)(i * (NBv) + nb) *    \
                     4096, BST_W * 4, m);                                     \
        }                                                                     \
    };                                                                        \
    float acc[4][8][4];                                                       \
    _Pragma("unroll") for (int mt = 0; mt < 4; mt++)                          \
        _Pragma("unroll") for (int nt = 0; nt < 8; nt++)                      \
            _Pragma("unroll") for (int i = 0; i < 4; i++)                     \
                acc[mt][nt][i] = 0.f;                                         \
    issue(0);                                                                 \
    issue(1);                                                                 \
    for (int i = 0; i < KC32; i++) {                                          \
        const int st = i & 1;                                                 \
        mbar_wait(mb0 + st * 8, (i >> 1) & 1);                                \
        const uint32_t* As = gsm + st * STG_W;                                \
        const uint32_t* Bs = As + AST_W;                                      \
        _Pragma("unroll") for (int ks8 = 0; ks8 < 4; ks8++) {                 \
            uint32_t a[4][4], b[8][2];                                        \
            _Pragma("unroll") for (int mt = 0; mt < 4; mt++) {                \
                uint4 av = *(const uint4*)&As[                                \
                    ((warpm * 16 + mt * 4 + ks8) * 32 + lane) * 4];           \
                a[mt][0] = av.x; a[mt][1] = av.y;                             \
                a[mt][2] = av.z; a[mt][3] = av.w;                             \
            }                                                                 \
            _Pragma("unroll") for (int nt = 0; nt < 8; nt++) {                \
                uint2 bv = *(const uint2*)&Bs[                                \
                    ((wn2 * 32 + nt * 4 + ks8) * 32 + lane) * 2];             \
                b[nt][0] = bv.x; b[nt][1] = bv.y;                             \
            }                                                                 \
            _Pragma("unroll") for (int mt = 0; mt < 4; mt++)                  \
                _Pragma("unroll") for (int nt = 0; nt < 8; nt++)              \
                    mma8(acc[mt][nt], a[mt], b[nt][0], b[nt][1]);             \
        }                                                                     \
        __syncthreads();                                                      \
        if (i + 2 < KC32) issue(i + 2);                                       \
    }

// ---------------------------------------------------------------------------
// GEMM 1: QKV projection with fused RoPE (R15 proven epilogues).
// ---------------------------------------------------------------------------
__global__ __launch_bounds__(256) void gemm_qkv(
    const float* __restrict__ Ap, const float* __restrict__ Bp,
    float* __restrict__ Qo, float* __restrict__ Ko, float* __restrict__ Vo,
    const float* __restrict__ cb, const float* __restrict__ sb) {
    GEMM_MAINLOOP(Ap, Bp, 24)

    const int col0 = nb * 128 + wn;             // 64-col slice start
    const int type = col0 >> 10;                // 0=q, 1=k, 2=v
    const int h = (col0 >> 6) & 15;
    const float qsc = 0.125f * 1.4426950408889634f;

    if (type == 0) {
#pragma unroll
        for (int mt = 0; mt < 4; mt++) {
#pragma unroll
            for (int e2 = 0; e2 < 2; e2++) {
                int r = bm + wm + mt * 16 + lr + 8 * e2;
                int s = r & 2047, bbx = r >> 11;
                float* dst = Qo + ((size_t)(bbx * Hh + h) * Ss + s) * 64;
                const float* cr = cb + s * 64;
                const float* sr = sb + s * 64;
#pragma unroll
                for (int nt = 0; nt < 4; nt++) {
                    int dlo = nt * 8 + (lq << 1);
                    float2 clo = *(const float2*)&cr[dlo];
                    float2 slo = *(const float2*)&sr[dlo];
                    float2 chi = *(const float2*)&cr[dlo + 32];
                    float2 shi = *(const float2*)&sr[dlo + 32];
                    float al0 = acc[mt][nt][2 * e2], al1 = acc[mt][nt][2 * e2 + 1];
                    float ah0 = acc[mt][nt + 4][2 * e2], ah1 = acc[mt][nt + 4][2 * e2 + 1];
                    float ol0 = (al0 * clo.x - ah0 * slo.x) * qsc;
                    float ol1 = (al1 * clo.y - ah1 * slo.y) * qsc;
                    float oh0 = (ah0 * chi.x + al0 * shi.x) * qsc;
                    float oh1 = (ah1 * chi.y + al1 * shi.y) * qsc;
                    *(float2*)&dst[dlo] = make_float2(f2tff(ol0), f2tff(ol1));
                    *(float2*)&dst[dlo + 32] = make_float2(f2tff(oh0), f2tff(oh1));
                }
            }
        }
    } else if (type == 1) {
#pragma unroll
        for (int mt = 0; mt < 4; mt++) {
#pragma unroll
            for (int e2 = 0; e2 < 2; e2++) {
                int r = bm + wm + mt * 16 + lr + 8 * e2;
                int s = r & 2047, bbx = r >> 11;
                float* dst = Ko + ((size_t)(bbx * Hh + h) * Ss + (s & ~63)) * 64;
                int rr = s & 63;
                int ntv = rr >> 3, lrv = rr & 7;
                const float* cr = cb + s * 64;
                const float* sr = sb + s * 64;
#pragma unroll
                for (int nt = 0; nt < 4; nt++) {
                    int dlo = nt * 8 + (lq << 1);
                    float2 clo = *(const float2*)&cr[dlo];
                    float2 slo = *(const float2*)&sr[dlo];
                    float2 chi = *(const float2*)&cr[dlo + 32];
                    float2 shi = *(const float2*)&sr[dlo + 32];
                    float al0 = acc[mt][nt][2 * e2], al1 = acc[mt][nt][2 * e2 + 1];
                    float ah0 = acc[mt][nt + 4][2 * e2], ah1 = acc[mt][nt + 4][2 * e2 + 1];
                    float v4[4] = {al0 * clo.x - ah0 * slo.x,
                                   al1 * clo.y - ah1 * slo.y,
                                   ah0 * chi.x + al0 * shi.x,
                                   ah1 * chi.y + al1 * shi.y};
                    int d4[4] = {dlo, dlo + 1, dlo + 32, dlo + 33};
#pragma unroll
                    for (int j = 0; j < 4; j++) {
                        int d = d4[j];
                        int k8 = d >> 3, e = (d >> 2) & 1, lqv = d & 3;
                        dst[2 * ((k8 * 8 + ntv) * 32 + 4 * lrv + lqv) + e] =
                            f2tff(v4[j]);
                    }
                }
            }
        }
    } else {
#pragma unroll
        for (int mt = 0; mt < 4; mt++) {
#pragma unroll
            for (int e2 = 0; e2 < 2; e2++) {
                int r = bm + wm + mt * 16 + lr + 8 * e2;
                int s = r & 2047, bbx = r >> 11;
                float* dst = Vo + ((size_t)(bbx * Hh + h) * Ss + (s & ~63)) * 64;
                int rr = s & 63;
                int k8v = rr >> 3, g = rr & 7;
                int lqv = g >> 1, ev = g & 1;       // permutation baked in
#pragma unroll
                for (int nt = 0; nt < 8; nt++) {
                    int d0 = nt * 8 + (lq << 1);
                    float v0 = acc[mt][nt][2 * e2], v1 = acc[mt][nt][2 * e2 + 1];
                    int lrv0 = d0 & 7, lrv1 = (d0 + 1) & 7;
                    dst[2 * ((k8v * 8 + nt) * 32 + 4 * lrv0 + lqv) + ev] = f2tff(v0);
                    dst[2 * ((k8v * 8 + nt) * 32 + 4 * lrv1 + lqv) + ev] = f2tff(v1);
                }
            }
        }
    }
}

// ---------------------------------------------------------------------------
// GEMM 2: output projection, plain row-major epilogue.
// ---------------------------------------------------------------------------
__global__ __launch_bounds__(256) void gemm_out(
    const float* __restrict__ Ap, const float* __restrict__ Bp,
    float* __restrict__ C) {
    GEMM_MAINLOOP(Ap, Bp, 8)

#pragma unroll
    for (int mt = 0; mt < 4; mt++)
#pragma unroll
        for (int nt = 0; nt < 8; nt++) {
            int row = bm + wm + mt * 16 + lr;
            int col = (nb << 7) + wn + nt * 8 + (lq << 1);
            *(float2*)&C[(size_t)row * 1024 + col] =
                make_float2(acc[mt][nt][0], acc[mt][nt][1]);
            *(float2*)&C[(size_t)(row + 8) * 1024 + col] =
                make_float2(acc[mt][nt][2], acc[mt][nt][3]);
        }
}

// ---------------------------------------------------------------------------
// Causal flash attention (R15 core) with PAIRED q-tiles for perfect load
// balance: CTA x handles qt = 15-x then qt = x (34 tile-units each, single
// wave at 2 CTAs/SM). LDS.64 pair-packed b-frags; frag-packed aop epilogue.
// ---------------------------------------------------------------------------
static constexpr int ATTN_STAGE_W = 8192;            // K 4096 + V 4096 words
static constexpr int ATTN_SMEM_BYTES = 2 * ATTN_STAGE_W * 4;   // 65536 B

__global__ __launch_bounds__(256, 2) void attn_kernel(
    const float* __restrict__ Q, const float* __restrict__ K,
    const float* __restrict__ V, float* __restrict__ AOP) {
    extern __shared__ uint32_t dynsmem[];

    const int h = blockIdx.y, b = blockIdx.z;
    const int tid = threadIdx.x, lane = tid & 31, warp = tid >> 5;
    const int lr = lane >> 2, lq = lane & 3;

    const size_t bh = (size_t)(b * Hh + h) * Ss;
    const float* Kg = K + bh * 64;
    const float* Vg = V + bh * 64;

    auto issue_tile = [&](int jt, int buf) {
        const float* kb = Kg + (size_t)(jt * 64) * 64;
        const float* vb = Vg + (size_t)(jt * 64) * 64;
        uint32_t* Kd = dynsmem + buf * ATTN_STAGE_W;
#pragma unroll
        for (int u = 0; u < 4; u++) {
            int w = (u * 256 + tid) * 4;
            cp16(&Kd[w], kb + w);
            cp16(&Kd[4096 + w], vb + w);
        }
        asm volatile("cp.async.commit_group;");
    };

    for (int qp = 0; qp < 2; qp++) {
        const int qt = qp ? blockIdx.x : (15 - blockIdx.x);
        const int q0 = qt * 128;
        const float* Qg = Q + (bh + q0) * 64;

        uint32_t qf[8][4];
        {
            int r0 = warp * 16 + lr;
#pragma unroll
            for (int k8 = 0; k8 < 8; k8++) {
                int c = k8 * 8 + lq;
                qf[k8][0] = __float_as_uint(Qg[r0 * 64 + c]);
                qf[k8][1] = __float_as_uint(Qg[(r0 + 8) * 64 + c]);
                qf[k8][2] = __float_as_uint(Qg[r0 * 64 + c + 4]);
                qf[k8][3] = __float_as_uint(Qg[(r0 + 8) * 64 + c + 4]);
            }
        }

        float o[8][4];
#pragma unroll
        for (int dn = 0; dn < 8; dn++)
#pragma unroll
            for (int i = 0; i < 4; i++) o[dn][i] = 0.f;
        float m0 = -1e30f, m1 = -1e30f, l0 = 0.f, l1 = 0.f;

        const int jmax = 2 * qt + 1;
        issue_tile(0, 0);

        for (int jt = 0; jt <= jmax; jt++) {
            const int cur = jt & 1;
            if (jt < jmax) {
                issue_tile(jt + 1, cur ^ 1);
                asm volatile("cp.async.wait_group 1;");
            } else {
                asm volatile("cp.async.wait_group 0;");
            }
            __syncthreads();

            const uint32_t* Ksb = dynsmem + cur * ATTN_STAGE_W;
            const uint32_t* Vsb = Ksb + 4096;

            float sc[8][4];
#pragma unroll
            for (int nt = 0; nt < 8; nt++)
#pragma unroll
                for (int i = 0; i < 4; i++) sc[nt][i] = 0.f;
#pragma unroll
            for (int k8 = 0; k8 < 8; k8++)
#pragma unroll
                for (int nt = 0; nt < 8; nt++) {
                    uint2 kv = *(const uint2*)&Ksb[((k8 * 8 + nt) * 32 + lane) * 2];
                    mma8(sc[nt], qf[k8], kv.x, kv.y);
                }

            if (jt >= 2 * qt) {
                int r1 = q0 + warp * 16 + lr;
#pragma unroll
                for (int nt = 0; nt < 8; nt++) {
                    int key = jt * 64 + nt * 8 + (lq << 1);
                    if (key > r1) sc[nt][0] = -1e30f;
                    if (key + 1 > r1) sc[nt][1] = -1e30f;
                    if (key > r1 + 8) sc[nt][2] = -1e30f;
                    if (key + 1 > r1 + 8) sc[nt][3] = -1e30f;
                }
            }

            float mx0 = -1e30f, mx1 = -1e30f;
#pragma unroll
            for (int nt = 0; nt < 8; nt++) {
                mx0 = fmaxf(mx0, fmaxf(sc[nt][0], sc[nt][1]));
                mx1 = fmaxf(mx1, fmaxf(sc[nt][2], sc[nt][3]));
            }
            mx0 = fmaxf(mx0, __shfl_xor_sync(0xffffffffu, mx0, 1));
            mx0 = fmaxf(mx0, __shfl_xor_sync(0xffffffffu, mx0, 2));
            mx1 = fmaxf(mx1, __shfl_xor_sync(0xffffffffu, mx1, 1));
            mx1 = fmaxf(mx1, __shfl_xor_sync(0xffffffffu, mx1, 2));
            float mn0 = fmaxf(m0, mx0), mn1 = fmaxf(m1, mx1);
            float fac0 = ex2(m0 - mn0), fac1 = ex2(m1 - mn1);

            float s0 = 0.f, s1 = 0.f;
#pragma unroll
            for (int nt = 0; nt < 8; nt++) {
                float p0 = ex2(sc[nt][0] - mn0);
                float p1 = ex2(sc[nt][1] - mn0);
                float p2 = ex2(sc[nt][2] - mn1);
                float p3 = ex2(sc[nt][3] - mn1);
                s0 += p0 + p1;
                s1 += p2 + p3;
                sc[nt][0] = p0;     // raw fp32 -> mma (HW tf32 truncation)
                sc[nt][1] = p1;
                sc[nt][2] = p2;
                sc[nt][3] = p3;
            }
            s0 += __shfl_xor_sync(0xffffffffu, s0, 1);
            s0 += __shfl_xor_sync(0xffffffffu, s0, 2);
            s1 += __shfl_xor_sync(0xffffffffu, s1, 1);
            s1 += __shfl_xor_sync(0xffffffffu, s1, 2);
            l0 = l0 * fac0 + s0;
            l1 = l1 * fac1 + s1;
            m0 = mn0;
            m1 = mn1;
#pragma unroll
            for (int dn = 0; dn < 8; dn++) {
                o[dn][0] *= fac0; o[dn][1] *= fac0;
                o[dn][2] *= fac1; o[dn][3] *= fac1;
            }

#pragma unroll
            for (int k8 = 0; k8 < 8; k8++) {
                uint32_t af[4] = {__float_as_uint(sc[k8][0]), __float_as_uint(sc[k8][2]),
                                  __float_as_uint(sc[k8][1]), __float_as_uint(sc[k8][3])};
#pragma unroll
                for (int dn = 0; dn < 8; dn++) {
                    uint2 vv = *(const uint2*)&Vsb[((k8 * 8 + dn) * 32 + lane) * 2];
                    mma8(o[dn], af, vv.x, vv.y);
                }
            }
            __syncthreads();
        }

        // ---- epilogue: normalize + tf32, write FRAGMENT-PACKED aop ----
        float i0 = 1.0f / l0, i1 = 1.0f / l1;
        int grow = b * Ss + q0 + warp * 16 + lr;

        auto paddr = [](int row, int c) -> size_t {
            int kc = c >> 5;
            int mb = row >> 8;
            int wm4 = (row >> 6) & 3;
            int mt = (row >> 4) & 3;
            int lane2 = ((row & 7) << 2) | (c & 3);
            int r = (((c >> 2) & 1) << 1) | ((row >> 3) & 1);
            int ks8 = (c >> 3) & 3;
            return (size_t)(kc * 16 + mb) * 8192 +
                   (size_t)((((wm4 * 4 + mt) * 4 + ks8) * 32 + lane2) * 4 + r);
        };

#pragma unroll
        for (int dn = 0; dn < 8; dn++) {
            int cbase = h * 64 + dn * 8 + (lq << 1);
            AOP[paddr(grow, cbase)]         = f2tff(o[dn][0] * i0);
            AOP[paddr(grow, cbase + 1)]     = f2tff(o[dn][1] * i0);
            AOP[paddr(grow + 8, cbase)]     = f2tff(o[dn][2] * i1);
            AOP[paddr(grow + 8, cbase + 1)] = f2tff(o[dn][3] * i1);
        }
    }
}

// ---------------------------------------------------------------------------
extern "C" void kernel_launch(void* const* d_in, const int* in_sizes, int n_in,
                              void* d_out, int out_size) {
    const float* x = (const float*)d_in[0];
    const float* w_qkv = (const float*)d_in[1];
    const float* w_out = (const float*)d_in[2];
    const float* freqs = (const float*)d_in[3];
    float* out = (float*)d_out;

    float *q, *k, *v, *xp, *wp, *wop, *aop, *cb, *sb;
    cudaGetSymbolAddress((void**)&q, g_q);
    cudaGetSymbolAddress((void**)&k, g_k);
    cudaGetSymbolAddress((void**)&v, g_v);
    cudaGetSymbolAddress((void**)&xp, g_xp);
    cudaGetSymbolAddress((void**)&wp, g_wp);
    cudaGetSymbolAddress((void**)&wop, g_wop);
    cudaGetSymbolAddress((void**)&aop, g_aop);
    cudaGetSymbolAddress((void**)&cb, g_cos);
    cudaGetSymbolAddress((void**)&sb, g_sin);

    cudaFuncSetAttribute(attn_kernel,
                         cudaFuncAttributeMaxDynamicSharedMemorySize,
                         ATTN_SMEM_BYTES);
    cudaFuncSetAttribute(gemm_qkv,
                         cudaFuncAttributeMaxDynamicSharedMemorySize,
                         GEMM_SMEM);
    cudaFuncSetAttribute(gemm_out,
                         cudaFuncAttributeMaxDynamicSharedMemorySize,
                         GEMM_SMEM);

    // 0) Pack operands (fragment order) + trig tables
    pack_a<<<4096, 256>>>(x, xp);                       // 1M quads
    pack_b<<<(32 * 24 * 2048) / 256, 256>>>(w_qkv, wp, 3072);
    pack_b<<<(32 * 8 * 2048) / 256, 256>>>(w_out, wop, 1024);
    trig_kernel<<<(Ss * DH) / 256, 256>>>(freqs, cb, sb);

    // 1) QKV projection + fused RoPE -> q row-major, k/v pair-packed
    gemm_qkv<<<dim3(24, 16), 256, GEMM_SMEM>>>(xp, wp, q, k, v, cb, sb);
    // 2) Causal flash attention (paired q-tiles; writes frag-packed aop)
    attn_kernel<<<dim3(8, Hh, Bb), 256, ATTN_SMEM_BYTES>>>(q, k, v, aop);
    // 3) Output projection
    gemm_out<<<dim3(8, 16), 256, GEMM_SMEM>>>(aop, wop, out);
}

// round 17
// speedup vs baseline: 1.1920x; 1.0067x over previous
#include <cuda_runtime.h>
#include <cstdint>

// Problem constants
static constexpr int Bb = 2, Ss = 2048, Hh = 16, DH = 64, Dd = 1024;
static constexpr int KC32 = 32;                 // 1024 / 32 k-steps

// Scratch (static device globals — no allocations allowed)
__device__ float g_q[Bb * Hh * Ss * DH];        // rope'd, scaled(*log2e), tf32
__device__ float g_k[Bb * Hh * Ss * DH];        // fragment-PAIR packed per 64-row tile
__device__ float g_v[Bb * Hh * Ss * DH];        // fragment-PAIR packed (perm baked)
__device__ float g_xp[32 * 4096 * 32];          // frag-packed A gemm1
__device__ float g_wp[32 * 24 * 4096];          // frag-packed B w_qkv
__device__ float g_wop[32 * 8 * 4096];          // frag-packed B w_out
__device__ float g_aop[32 * 4096 * 32];         // frag-packed A gemm2
__device__ float g_cos[Ss * DH];                // cos(freqs)
__device__ float g_sin[Ss * DH];                // sin(freqs)

__device__ __forceinline__ uint32_t f2tf(float f) {
    uint32_t u;
    asm("cvt.rna.tf32.f32 %0, %1;" : "=r"(u) : "f"(f));
    return u;
}
__device__ __forceinline__ float f2tff(float f) { return __uint_as_float(f2tf(f)); }

__device__ __forceinline__ float ex2(float x) {
    float y;
    asm("ex2.approx.f32 %0, %1;" : "=f"(y) : "f"(x));
    return y;
}

__device__ __forceinline__ void cp16(void* smem_ptr, const void* gptr) {
    uint32_t sa = (uint32_t)__cvta_generic_to_shared(smem_ptr);
    asm volatile("cp.async.ca.shared.global [%0], [%1], 16;"
                 :: "r"(sa), "l"(gptr));
}

__device__ __forceinline__ void mma8(float (&c)[4], const uint32_t (&a)[4],
                                     uint32_t b0, uint32_t b1) {
    asm volatile(
        "mma.sync.aligned.m16n8k8.row.col.f32.tf32.tf32.f32 "
        "{%0,%1,%2,%3}, {%4,%5,%6,%7}, {%8,%9}, {%0,%1,%2,%3};"
        : "+f"(c[0]), "+f"(c[1]), "+f"(c[2]), "+f"(c[3])
        : "r"(a[0]), "r"(a[1]), "r"(a[2]), "r"(a[3]), "r"(b0), "r"(b1));
}

// ---- mbarrier + 1D bulk-copy helpers ----
__device__ __forceinline__ uint32_t s2u(const void* p) {
    return (uint32_t)__cvta_generic_to_shared(p);
}
__device__ __forceinline__ void mbar_init(uint32_t addr, uint32_t cnt) {
    asm volatile("mbarrier.init.shared.b64 [%0], %1;" :: "r"(addr), "r"(cnt));
}
__device__ __forceinline__ void mbar_expect_tx(uint32_t addr, uint32_t bytes) {
    asm volatile("mbarrier.arrive.expect_tx.shared.b64 _, [%0], %1;"
                 :: "r"(addr), "r"(bytes));
}
__device__ __forceinline__ void mbar_wait(uint32_t addr, uint32_t parity) {
    asm volatile(
        "{\n\t.reg .pred P;\n"
        "W%=:\n\t"
        "mbarrier.try_wait.parity.shared.b64 P, [%0], %1;\n\t"
        "@!P bra W%=;\n\t}"
        :: "r"(addr), "r"(parity) : "memory");
}
__device__ __forceinline__ void bulk_g2s(uint32_t dst, const void* src,
                                         uint32_t bytes, uint32_t mbar) {
    asm volatile(
        "cp.async.bulk.shared::cta.global.mbarrier::complete_tx::bytes "
        "[%0], [%1], %2, [%3];"
        :: "r"(dst), "l"(src), "r"(bytes), "r"(mbar) : "memory");
}

// ---------------------------------------------------------------------------
// Fragment-packed A/B pack kernels (R14 proven, unchanged).
// ---------------------------------------------------------------------------
__global__ __launch_bounds__(256) void pack_a(
    const float* __restrict__ X, float* __restrict__ Xp) {
    int idx = blockIdx.x * 256 + threadIdx.x;   // 1M quads
    int lane = idx & 31;
    int ks8 = (idx >> 5) & 3;
    int mt = (idx >> 7) & 3;
    int wm4 = (idx >> 9) & 3;
    int mb = (idx >> 11) & 15;
    int kc = idx >> 15;
    int row = mb * 256 + wm4 * 64 + mt * 16 + (lane >> 2);
    int c = kc * 32 + ks8 * 8 + (lane & 3);
    const float* xr = X + (size_t)row * 1024 + c;
    float4 q = make_float4(f2tff(xr[0]), f2tff(xr[8192]),      // +8 rows
                           f2tff(xr[4]), f2tff(xr[8196]));
    *(float4*)&Xp[(size_t)idx * 4] = q;
}

__global__ __launch_bounds__(256) void pack_b(
    const float* __restrict__ W, float* __restrict__ Wp, int N) {
    int idx = blockIdx.x * 256 + threadIdx.x;
    int NB = N >> 7;
    int per_kc = NB << 11;
    int kc = idx / per_kc;
    int rem = idx - kc * per_kc;
    int nb = rem >> 11;
    int w = rem & 2047;
    int lane = w & 31;
    int ks8 = (w >> 5) & 3;
    int nt = (w >> 7) & 7;
    int wn2 = (w >> 10) & 1;
    int col = nb * 128 + wn2 * 64 + nt * 8 + (lane >> 2);
    int k0 = kc * 32 + ks8 * 8 + (lane & 3);
    const float* wr = W + (size_t)k0 * N + col;
    *(float2*)&Wp[(size_t)idx * 2] =
        make_float2(f2tff(wr[0]), f2tff(wr[4 * N]));
}

// cos/sin tables for the fused-rope GEMM epilogue (precise sincosf, once).
__global__ __launch_bounds__(256) void trig_kernel(
    const float* __restrict__ freqs, float* __restrict__ cb,
    float* __restrict__ sb) {
    int i = blockIdx.x * 256 + threadIdx.x;     // 2048*64
    float s, c;
    sincosf(freqs[i], &s, &c);
    cb[i] = c;
    sb[i] = s;
}

// ---------------------------------------------------------------------------
// GEMM mainloop (R16 proven): 256x128 tile, BK=32, frag-packed smem, 2-stage
// pipeline (98.3KB smem -> 2 CTAs/SM).
// ---------------------------------------------------------------------------
static constexpr int AST_W = 256 * 32;          // 8192 words
static constexpr int BST_W = 32 * 128;          // 4096 words
static constexpr int STG_W = AST_W + BST_W;     // 12288 words = 49152 B
static constexpr int GEMM_SMEM = 2 * STG_W * 4; // 98304 B

#define GEMM_MAINLOOP(ApPtr, BpPtr, NBv)                                      \
    extern __shared__ uint32_t gsm[];                                         \
    __shared__ uint64_t gmb[2];                                               \
    const int tid = threadIdx.x, lane = tid & 31, warp = tid >> 5;            \
    const int wm = (warp >> 1) * 64, wn = (warp & 1) * 64;                    \
    const int warpm = warp >> 1, wn2 = warp & 1;                              \
    const int lr = lane >> 2, lq = lane & 3;                                  \
    const int bm = blockIdx.y * 256, nb = blockIdx.x;                         \
    const uint32_t mb0 = s2u(gmb);                                            \
    const uint32_t smem_base = s2u(gsm);                                      \
    if (tid == 0) {                                                           \
        mbar_init(mb0, 1);                                                    \
        mbar_init(mb0 + 8, 1);                                                \
        asm volatile("fence.proxy.async.shared::cta;" ::: "memory");          \
    }                                                                         \
    __syncthreads();                                                          \
    auto issue = [&](int i) {                                                 \
        if (tid == 0) {                                                       \
            int st = i & 1;                                                   \
            uint32_t m = mb0 + st * 8;                                        \
            uint32_t dst = smem_base + st * (STG_W * 4);                      \
            mbar_expect_tx(m, STG_W * 4);                                     \
            bulk_g2s(dst, (ApPtr) + (size_t)(i * 16 + blockIdx.y) * 8192,     \
                     AST_W * 4, m);                                           \
            bulk_g2s(dst + AST_W * 4, (BpPtr) + (size_t)(i * (NBv) + nb) *    \
                     4096, BST_W * 4, m);                                     \
        }                                                                     \
    };                                                                        \
    float acc[4][8][4];                                                       \
    _Pragma("unroll") for (int mt = 0; mt < 4; mt++)                          \
        _Pragma("unroll") for (int nt = 0; nt < 8; nt++)                      \
            _Pragma("unroll") for (int i = 0; i < 4; i++)                     \
                acc[mt][nt][i] = 0.f;                                         \
    issue(0);                                                                 \
    issue(1);                                                                 \
    for (int i = 0; i < KC32; i++) {                                          \
        const int st = i & 1;                                                 \
        mbar_wait(mb0 + st * 8, (i >> 1) & 1);                                \
        const uint32_t* As = gsm + st * STG_W;                                \
        const uint32_t* Bs = As + AST_W;                                      \
        _Pragma("unroll") for (int ks8 = 0; ks8 < 4; ks8++) {                 \
            uint32_t a[4][4], b[8][2];                                        \
            _Pragma("unroll") for (int mt = 0; mt < 4; mt++) {                \
                uint4 av = *(const uint4*)&As[                                \
                    ((warpm * 16 + mt * 4 + ks8) * 32 + lane) * 4];           \
                a[mt][0] = av.x; a[mt][1] = av.y;                             \
                a[mt][2] = av.z; a[mt][3] = av.w;                             \
            }                                                                 \
            _Pragma("unroll") for (int nt = 0; nt < 8; nt++) {                \
                uint2 bv = *(const uint2*)&Bs[                                \
                    ((wn2 * 32 + nt * 4 + ks8) * 32 + lane) * 2];             \
                b[nt][0] = bv.x; b[nt][1] = bv.y;                             \
            }                                                                 \
            _Pragma("unroll") for (int mt = 0; mt < 4; mt++)                  \
                _Pragma("unroll") for (int nt = 0; nt < 8; nt++)              \
                    mma8(acc[mt][nt], a[mt], b[nt][0], b[nt][1]);             \
        }                                                                     \
        __syncthreads();                                                      \
        if (i + 2 < KC32) issue(i + 2);                                       \
    }

// ---------------------------------------------------------------------------
// GEMM 1: QKV projection with fused RoPE (R15 proven epilogues).
// ---------------------------------------------------------------------------
__global__ __launch_bounds__(256) void gemm_qkv(
    const float* __restrict__ Ap, const float* __restrict__ Bp,
    float* __restrict__ Qo, float* __restrict__ Ko, float* __restrict__ Vo,
    const float* __restrict__ cb, const float* __restrict__ sb) {
    GEMM_MAINLOOP(Ap, Bp, 24)

    const int col0 = nb * 128 + wn;             // 64-col slice start
    const int type = col0 >> 10;                // 0=q, 1=k, 2=v
    const int h = (col0 >> 6) & 15;
    const float qsc = 0.125f * 1.4426950408889634f;

    if (type == 0) {
#pragma unroll
        for (int mt = 0; mt < 4; mt++) {
#pragma unroll
            for (int e2 = 0; e2 < 2; e2++) {
                int r = bm + wm + mt * 16 + lr + 8 * e2;
                int s = r & 2047, bbx = r >> 11;
                float* dst = Qo + ((size_t)(bbx * Hh + h) * Ss + s) * 64;
                const float* cr = cb + s * 64;
                const float* sr = sb + s * 64;
#pragma unroll
                for (int nt = 0; nt < 4; nt++) {
                    int dlo = nt * 8 + (lq << 1);
                    float2 clo = *(const float2*)&cr[dlo];
                    float2 slo = *(const float2*)&sr[dlo];
                    float2 chi = *(const float2*)&cr[dlo + 32];
                    float2 shi = *(const float2*)&sr[dlo + 32];
                    float al0 = acc[mt][nt][2 * e2], al1 = acc[mt][nt][2 * e2 + 1];
                    float ah0 = acc[mt][nt + 4][2 * e2], ah1 = acc[mt][nt + 4][2 * e2 + 1];
                    float ol0 = (al0 * clo.x - ah0 * slo.x) * qsc;
                    float ol1 = (al1 * clo.y - ah1 * slo.y) * qsc;
                    float oh0 = (ah0 * chi.x + al0 * shi.x) * qsc;
                    float oh1 = (ah1 * chi.y + al1 * shi.y) * qsc;
                    *(float2*)&dst[dlo] = make_float2(f2tff(ol0), f2tff(ol1));
                    *(float2*)&dst[dlo + 32] = make_float2(f2tff(oh0), f2tff(oh1));
                }
            }
        }
    } else if (type == 1) {
#pragma unroll
        for (int mt = 0; mt < 4; mt++) {
#pragma unroll
            for (int e2 = 0; e2 < 2; e2++) {
                int r = bm + wm + mt * 16 + lr + 8 * e2;
                int s = r & 2047, bbx = r >> 11;
                float* dst = Ko + ((size_t)(bbx * Hh + h) * Ss + (s & ~63)) * 64;
                int rr = s & 63;
                int ntv = rr >> 3, lrv = rr & 7;
                const float* cr = cb + s * 64;
                const float* sr = sb + s * 64;
#pragma unroll
                for (int nt = 0; nt < 4; nt++) {
                    int dlo = nt * 8 + (lq << 1);
                    float2 clo = *(const float2*)&cr[dlo];
                    float2 slo = *(const float2*)&sr[dlo];
                    float2 chi = *(const float2*)&cr[dlo + 32];
                    float2 shi = *(const float2*)&sr[dlo + 32];
                    float al0 = acc[mt][nt][2 * e2], al1 = acc[mt][nt][2 * e2 + 1];
                    float ah0 = acc[mt][nt + 4][2 * e2], ah1 = acc[mt][nt + 4][2 * e2 + 1];
                    float v4[4] = {al0 * clo.x - ah0 * slo.x,
                                   al1 * clo.y - ah1 * slo.y,
                                   ah0 * chi.x + al0 * shi.x,
                                   ah1 * chi.y + al1 * shi.y};
                    int d4[4] = {dlo, dlo + 1, dlo + 32, dlo + 33};
#pragma unroll
                    for (int j = 0; j < 4; j++) {
                        int d = d4[j];
                        int k8 = d >> 3, e = (d >> 2) & 1, lqv = d & 3;
                        dst[2 * ((k8 * 8 + ntv) * 32 + 4 * lrv + lqv) + e] =
                            f2tff(v4[j]);
                    }
                }
            }
        }
    } else {
#pragma unroll
        for (int mt = 0; mt < 4; mt++) {
#pragma unroll
            for (int e2 = 0; e2 < 2; e2++) {
                int r = bm + wm + mt * 16 + lr + 8 * e2;
                int s = r & 2047, bbx = r >> 11;
                float* dst = Vo + ((size_t)(bbx * Hh + h) * Ss + (s & ~63)) * 64;
                int rr = s & 63;
                int k8v = rr >> 3, g = rr & 7;
                int lqv = g >> 1, ev = g & 1;       // permutation baked in
#pragma unroll
                for (int nt = 0; nt < 8; nt++) {
                    int d0 = nt * 8 + (lq << 1);
                    float v0 = acc[mt][nt][2 * e2], v1 = acc[mt][nt][2 * e2 + 1];
                    int lrv0 = d0 & 7, lrv1 = (d0 + 1) & 7;
                    dst[2 * ((k8v * 8 + nt) * 32 + 4 * lrv0 + lqv) + ev] = f2tff(v0);
                    dst[2 * ((k8v * 8 + nt) * 32 + 4 * lrv1 + lqv) + ev] = f2tff(v1);
                }
            }
        }
    }
}

// ---------------------------------------------------------------------------
// GEMM 2: output projection, plain row-major epilogue.
// ---------------------------------------------------------------------------
__global__ __launch_bounds__(256) void gemm_out(
    const float* __restrict__ Ap, const float* __restrict__ Bp,
    float* __restrict__ C) {
    GEMM_MAINLOOP(Ap, Bp, 8)

#pragma unroll
    for (int mt = 0; mt < 4; mt++)
#pragma unroll
        for (int nt = 0; nt < 8; nt++) {
            int row = bm + wm + mt * 16 + lr;
            int col = (nb << 7) + wn + nt * 8 + (lq << 1);
            *(float2*)&C[(size_t)row * 1024 + col] =
                make_float2(acc[mt][nt][0], acc[mt][nt][1]);
            *(float2*)&C[(size_t)(row + 8) * 1024 + col] =
                make_float2(acc[mt][nt][2], acc[mt][nt][3]);
        }
}

// ---------------------------------------------------------------------------
// Causal flash attention (R16 core) + row-sums via mma (ones B-fragment in
// registers) + fully-masked-warp compute skip on the diagonal upper tile.
// ---------------------------------------------------------------------------
static constexpr int ATTN_STAGE_W = 8192;            // K 4096 + V 4096 words
static constexpr int ATTN_SMEM_BYTES = 2 * ATTN_STAGE_W * 4;   // 65536 B

__global__ __launch_bounds__(256, 2) void attn_kernel(
    const float* __restrict__ Q, const float* __restrict__ K,
    const float* __restrict__ V, float* __restrict__ AOP) {
    extern __shared__ uint32_t dynsmem[];

    const int h = blockIdx.y, b = blockIdx.z;
    const int tid = threadIdx.x, lane = tid & 31, warp = tid >> 5;
    const int lr = lane >> 2, lq = lane & 3;
    const uint32_t ONE = 0x3f800000u;

    const size_t bh = (size_t)(b * Hh + h) * Ss;
    const float* Kg = K + bh * 64;
    const float* Vg = V + bh * 64;

    auto issue_tile = [&](int jt, int buf) {
        const float* kb = Kg + (size_t)(jt * 64) * 64;
        const float* vb = Vg + (size_t)(jt * 64) * 64;
        uint32_t* Kd = dynsmem + buf * ATTN_STAGE_W;
#pragma unroll
        for (int u = 0; u < 4; u++) {
            int w = (u * 256 + tid) * 4;
            cp16(&Kd[w], kb + w);
            cp16(&Kd[4096 + w], vb + w);
        }
        asm volatile("cp.async.commit_group;");
    };

    for (int qp = 0; qp < 2; qp++) {
        const int qt = qp ? blockIdx.x : (15 - blockIdx.x);
        const int q0 = qt * 128;
        const float* Qg = Q + (bh + q0) * 64;

        uint32_t qf[8][4];
        {
            int r0 = warp * 16 + lr;
#pragma unroll
            for (int k8 = 0; k8 < 8; k8++) {
                int c = k8 * 8 + lq;
                qf[k8][0] = __float_as_uint(Qg[r0 * 64 + c]);
                qf[k8][1] = __float_as_uint(Qg[(r0 + 8) * 64 + c]);
                qf[k8][2] = __float_as_uint(Qg[r0 * 64 + c + 4]);
                qf[k8][3] = __float_as_uint(Qg[(r0 + 8) * 64 + c + 4]);
            }
        }

        float o[8][4];
#pragma unroll
        for (int dn = 0; dn < 8; dn++)
#pragma unroll
            for (int i = 0; i < 4; i++) o[dn][i] = 0.f;
        float osum[4] = {0.f, 0.f, 0.f, 0.f};
        float m0 = -1e30f, m1 = -1e30f;

        const int warp_rmax = q0 + warp * 16 + 15;
        const int jmax = 2 * qt + 1;
        issue_tile(0, 0);

        for (int jt = 0; jt <= jmax; jt++) {
            const int cur = jt & 1;
            if (jt < jmax) {
                issue_tile(jt + 1, cur ^ 1);
                asm volatile("cp.async.wait_group 1;");
            } else {
                asm volatile("cp.async.wait_group 0;");
            }
            __syncthreads();

            // Fully-masked warp on the diagonal upper tile: state provably
            // unchanged; skip compute, keep barrier structure intact.
            if (jt * 64 <= warp_rmax) {
                const uint32_t* Ksb = dynsmem + cur * ATTN_STAGE_W;
                const uint32_t* Vsb = Ksb + 4096;

                float sc[8][4];
#pragma unroll
                for (int nt = 0; nt < 8; nt++)
#pragma unroll
                    for (int i = 0; i < 4; i++) sc[nt][i] = 0.f;
#pragma unroll
                for (int k8 = 0; k8 < 8; k8++)
#pragma unroll
                    for (int nt = 0; nt < 8; nt++) {
                        uint2 kv = *(const uint2*)&Ksb[((k8 * 8 + nt) * 32 + lane) * 2];
                        mma8(sc[nt], qf[k8], kv.x, kv.y);
                    }

                if (jt >= 2 * qt) {
                    int r1 = q0 + warp * 16 + lr;
#pragma unroll
                    for (int nt = 0; nt < 8; nt++) {
                        int key = jt * 64 + nt * 8 + (lq << 1);
                        if (key > r1) sc[nt][0] = -1e30f;
                        if (key + 1 > r1) sc[nt][1] = -1e30f;
                        if (key > r1 + 8) sc[nt][2] = -1e30f;
                        if (key + 1 > r1 + 8) sc[nt][3] = -1e30f;
                    }
                }

                float mx0 = -1e30f, mx1 = -1e30f;
#pragma unroll
                for (int nt = 0; nt < 8; nt++) {
                    mx0 = fmaxf(mx0, fmaxf(sc[nt][0], sc[nt][1]));
                    mx1 = fmaxf(mx1, fmaxf(sc[nt][2], sc[nt][3]));
                }
                mx0 = fmaxf(mx0, __shfl_xor_sync(0xffffffffu, mx0, 1));
                mx0 = fmaxf(mx0, __shfl_xor_sync(0xffffffffu, mx0, 2));
                mx1 = fmaxf(mx1, __shfl_xor_sync(0xffffffffu, mx1, 1));
                mx1 = fmaxf(mx1, __shfl_xor_sync(0xffffffffu, mx1, 2));
                float mn0 = fmaxf(m0, mx0), mn1 = fmaxf(m1, mx1);
                float fac0 = ex2(m0 - mn0), fac1 = ex2(m1 - mn1);

#pragma unroll
                for (int nt = 0; nt < 8; nt++) {
                    sc[nt][0] = ex2(sc[nt][0] - mn0);   // raw fp32 -> mma
                    sc[nt][1] = ex2(sc[nt][1] - mn0);
                    sc[nt][2] = ex2(sc[nt][2] - mn1);
                    sc[nt][3] = ex2(sc[nt][3] - mn1);
                }
                m0 = mn0;
                m1 = mn1;
#pragma unroll
                for (int dn = 0; dn < 8; dn++) {
                    o[dn][0] *= fac0; o[dn][1] *= fac0;
                    o[dn][2] *= fac1; o[dn][3] *= fac1;
                }
                osum[0] *= fac0; osum[1] *= fac0;
                osum[2] *= fac1; osum[3] *= fac1;

#pragma unroll
                for (int k8 = 0; k8 < 8; k8++) {
                    uint32_t af[4] = {__float_as_uint(sc[k8][0]),
                                      __float_as_uint(sc[k8][2]),
                                      __float_as_uint(sc[k8][1]),
                                      __float_as_uint(sc[k8][3])};
#pragma unroll
                    for (int dn = 0; dn < 8; dn++) {
                        uint2 vv = *(const uint2*)&Vsb[((k8 * 8 + dn) * 32 + lane) * 2];
                        mma8(o[dn], af, vv.x, vv.y);
                    }
                    mma8(osum, af, ONE, ONE);   // P @ ones = row sums
                }
            }
            __syncthreads();
        }

        // ---- epilogue: normalize + tf32, write FRAGMENT-PACKED aop ----
        float i0 = 1.0f / osum[0], i1 = 1.0f / osum[2];
        int grow = b * Ss + q0 + warp * 16 + lr;

        auto paddr = [](int row, int c) -> size_t {
            int kc = c >> 5;
            int mb = row >> 8;
            int wm4 = (row >> 6) & 3;
            int mt = (row >> 4) & 3;
            int lane2 = ((row & 7) << 2) | (c & 3);
            int r = (((c >> 2) & 1) << 1) | ((row >> 3) & 1);
            int ks8 = (c >> 3) & 3;
            return (size_t)(kc * 16 + mb) * 8192 +
                   (size_t)((((wm4 * 4 + mt) * 4 + ks8) * 32 + lane2) * 4 + r);
        };

#pragma unroll
        for (int dn = 0; dn < 8; dn++) {
            int cbase = h * 64 + dn * 8 + (lq << 1);
            AOP[paddr(grow, cbase)]         = f2tff(o[dn][0] * i0);
            AOP[paddr(grow, cbase + 1)]     = f2tff(o[dn][1] * i0);
            AOP[paddr(grow + 8, cbase)]     = f2tff(o[dn][2] * i1);
            AOP[paddr(grow + 8, cbase + 1)] = f2tff(o[dn][3] * i1);
        }
    }
}

// ---------------------------------------------------------------------------
extern "C" void kernel_launch(void* const* d_in, const int* in_sizes, int n_in,
                              void* d_out, int out_size) {
    const float* x = (const float*)d_in[0];
    const float* w_qkv = (const float*)d_in[1];
    const float* w_out = (const float*)d_in[2];
    const float* freqs = (const float*)d_in[3];
    float* out = (float*)d_out;

    float *q, *k, *v, *xp, *wp, *wop, *aop, *cb, *sb;
    cudaGetSymbolAddress((void**)&q, g_q);
    cudaGetSymbolAddress((void**)&k, g_k);
    cudaGetSymbolAddress((void**)&v, g_v);
    cudaGetSymbolAddress((void**)&xp, g_xp);
    cudaGetSymbolAddress((void**)&wp, g_wp);
    cudaGetSymbolAddress((void**)&wop, g_wop);
    cudaGetSymbolAddress((void**)&aop, g_aop);
    cudaGetSymbolAddress((void**)&cb, g_cos);
    cudaGetSymbolAddress((void**)&sb, g_sin);

    cudaFuncSetAttribute(attn_kernel,
                         cudaFuncAttributeMaxDynamicSharedMemorySize,
                         ATTN_SMEM_BYTES);
    cudaFuncSetAttribute(gemm_qkv,
                         cudaFuncAttributeMaxDynamicSharedMemorySize,
                         GEMM_SMEM);
    cudaFuncSetAttribute(gemm_out,
                         cudaFuncAttributeMaxDynamicSharedMemorySize,
                         GEMM_SMEM);

    // 0) Pack operands (fragment order) + trig tables
    pack_a<<<4096, 256>>>(x, xp);                       // 1M quads
    pack_b<<<(32 * 24 * 2048) / 256, 256>>>(w_qkv, wp, 3072);
    pack_b<<<(32 * 8 * 2048) / 256, 256>>>(w_out, wop, 1024);
    trig_kernel<<<(Ss * DH) / 256, 256>>>(freqs, cb, sb);

    // 1) QKV projection + fused RoPE -> q row-major, k/v pair-packed
    gemm_qkv<<<dim3(24, 16), 256, GEMM_SMEM>>>(xp, wp, q, k, v, cb, sb);
    // 2) Causal flash attention (paired q-tiles; mma row sums)
    attn_kernel<<<dim3(8, Hh, Bb), 256, ATTN_SMEM_BYTES>>>(q, k, v, aop);
    // 3) Output projection
    gemm_out<<<dim3(8, 16), 256, GEMM_SMEM>>>(aop, wop, out);
}